// round 13
// baseline (speedup 1.0000x reference)
#include <cuda_runtime.h>
#include <cuda_bf16.h>
#include <cuda_fp16.h>
#include <cstdint>

// Problem constants
constexpr int BATCH = 4;
constexpr int SEQ   = 2048;
constexpr int HID   = 512;
constexpr int HEADS = 8;
constexpr int HDIM  = 64;
constexpr int MROWS = BATCH * SEQ;           // 8192
constexpr int MH    = MROWS * HID;           // 4194304
constexpr int BH    = BATCH * HEADS;         // 32

// Scratch (device globals; no allocation allowed)
__device__ __half g_Sh[3 * MH];   // split activations (GEMM A, fp16 hi): [z][token][512]
__device__ __half g_Sl[3 * MH];   // fp16 lo residuals
__device__ __half g_Hh[3 * MH];   // head-layout Q/K/V fp16 hi: [z][b*8+h][s][64]
__device__ __half g_Hl[3 * MH];   // fp16 lo (used for Q and K)
__device__ __half g_Ch[MH];       // split ctx: [token][512]
__device__ __half g_Cl[MH];
__device__ __half g_Wth[4 * HID * HID];   // Wt fp16 hi
__device__ __half g_Wtl[4 * HID * HID];   // Wt fp16 lo
// Split-K attention partials (fp32, unnormalized): [split][bh][row][64], l: [split][bh][row]
__device__ float  g_Po[2 * BH * SEQ * HDIM];
__device__ float  g_Pl[2 * BH * SEQ];

#define SWZ(o) ((o) ^ (((o) >> 3) & 0x70))

__device__ __forceinline__ uint32_t smem_u32(const void* p) {
    uint32_t a;
    asm("{ .reg .u64 t; cvta.to.shared.u64 t, %1; cvt.u32.u64 %0, t; }" : "=r"(a) : "l"(p));
    return a;
}
// fp16 split: value = hi + lo to ~2^-22
__device__ __forceinline__ void split2h(float a, float b, uint32_t& hi, uint32_t& lo) {
    __half2 h = __floats2half2_rn(a, b);
    float ra = a - __half2float(__low2half(h));
    float rb = b - __half2float(__high2half(h));
    hi = *reinterpret_cast<uint32_t*>(&h);
    __half2 l = __floats2half2_rn(ra, rb);
    lo = *reinterpret_cast<uint32_t*>(&l);
}
// d = {lo: lo_src, hi: hi_src}
__device__ __forceinline__ uint32_t cvt_f16x2(float hi_src, float lo_src) {
    uint32_t d;
    asm("cvt.rn.f16x2.f32 %0, %1, %2;" : "=r"(d) : "f"(hi_src), "f"(lo_src));
    return d;
}
__device__ __forceinline__ uint32_t exp2_f16x2(uint32_t x) {
    uint32_t d;
    asm("ex2.approx.f16x2 %0, %1;" : "=r"(d) : "r"(x));
    return d;
}
__device__ __forceinline__ void ldmatrix_x4(uint32_t* r, uint32_t addr) {
    asm volatile("ldmatrix.sync.aligned.m8n8.x4.shared.b16 {%0,%1,%2,%3}, [%4];"
                 : "=r"(r[0]), "=r"(r[1]), "=r"(r[2]), "=r"(r[3]) : "r"(addr));
}
__device__ __forceinline__ void ldmatrix_x4_t(uint32_t* r, uint32_t addr) {
    asm volatile("ldmatrix.sync.aligned.m8n8.x4.trans.shared.b16 {%0,%1,%2,%3}, [%4];"
                 : "=r"(r[0]), "=r"(r[1]), "=r"(r[2]), "=r"(r[3]) : "r"(addr));
}
__device__ __forceinline__ void mma_f16(float* d, const uint32_t* a, const uint32_t* b) {
    asm volatile("mma.sync.aligned.m16n8k16.row.col.f32.f16.f16.f32 "
                 "{%0,%1,%2,%3}, {%4,%5,%6,%7}, {%8,%9}, {%0,%1,%2,%3};"
                 : "+f"(d[0]), "+f"(d[1]), "+f"(d[2]), "+f"(d[3])
                 : "r"(a[0]), "r"(a[1]), "r"(a[2]), "r"(a[3]), "r"(b[0]), "r"(b[1]));
}
__device__ __forceinline__ void cp16(uint32_t s, const void* g) {
    asm volatile("cp.async.cg.shared.global [%0], [%1], 16;" :: "r"(s), "l"(g));
}
#define CP_COMMIT() asm volatile("cp.async.commit_group;" ::: "memory")
#define CP_WAIT0()  asm volatile("cp.async.wait_group 0;" ::: "memory")

// Static softmax shift (log2 domain). p = 2^(S' - SHIFT2), S' = log2e * S.
constexpr float SHIFT2 = 6.0f;
constexpr float LOG2E  = 1.4426950408889634f;

// ===========================================================================
// Prep kernels (fp16 hi/lo splits)
// ===========================================================================
__global__ void prep_weights(const float* __restrict__ Wq, const float* __restrict__ Wk,
                             const float* __restrict__ Wv, const float* __restrict__ Wo,
                             __half* __restrict__ Wth, __half* __restrict__ Wtl)
{
    int idx = blockIdx.x * blockDim.x + threadIdx.x;
    int mat = idx >> 18;
    int r   = idx & 262143;
    int n   = r >> 9;
    int k   = r & 511;
    const float* W = (mat == 0) ? Wq : (mat == 1) ? Wk : (mat == 2) ? Wv : Wo;
    float w  = W[k * 512 + n];
    __half hi = __float2half_rn(w);
    float lo = w - __half2float(hi);
    Wth[idx] = hi;
    Wtl[idx] = __float2half_rn(lo);
}

__global__ void prep_acts(const float* __restrict__ q, const float* __restrict__ k,
                          const float* __restrict__ v,
                          __half* __restrict__ Sh, __half* __restrict__ Sl)
{
    int i = blockIdx.x * blockDim.x + threadIdx.x;   // float4 units
    const int per = MH / 4;
    int z = i / per, r = i - z * per;
    const float* src = (z == 0) ? q : (z == 1) ? k : v;
    float4 x = ((const float4*)src)[r];
    uint32_t h0, l0, h1, l1;
    split2h(x.x, x.y, h0, l0);
    split2h(x.z, x.w, h1, l1);
    ((uint2*)Sh)[i] = make_uint2(h0, h1);
    ((uint2*)Sl)[i] = make_uint2(l0, l1);
}

// ===========================================================================
// HMMA fp16 GEMM v4 (unchanged from R12): CTA 128x64, 4 warps, 2 CTAs/SM.
// ===========================================================================
constexpr int GB_AH = 0;
constexpr int GB_AL = 16384;
constexpr int GB_BH = 32768;
constexpr int GB_BL = 40960;
constexpr int GB_SZ = 49152;
constexpr int GEMM_SMEM = 98304;

template<int MODE>
__global__ __launch_bounds__(128, 2)
void gemm_v4(const __half* __restrict__ Ah_, const __half* __restrict__ Al_,
             const __half* __restrict__ Bh_, const __half* __restrict__ Bl_,
             const float* __restrict__ b0, const float* __restrict__ b1,
             const float* __restrict__ b2,
             float* __restrict__ C, __half* __restrict__ Oh, __half* __restrict__ Ol)
{
    extern __shared__ __align__(1024) char smem[];
    const uint32_t sb = smem_u32(smem);
    const int tid = threadIdx.x, wid = tid >> 5, lane = tid & 31;
    const int n0 = blockIdx.x * 64, m0 = blockIdx.y * 128;
    const int z  = (MODE == 1) ? blockIdx.z : 0;
    const bool three = (MODE == 1) && (z != 2);

    const __half* Ah = Ah_ + (size_t)z * MH;
    const __half* Al = Al_ + (size_t)z * MH;
    const __half* Bh = Bh_ + (size_t)z * HID * HID;
    const __half* Bl = Bl_ + (size_t)z * HID * HID;
    const float* bias = (z == 0) ? b0 : (z == 1) ? b1 : b2;
    const float scale = (MODE == 1 && z == 0) ? 0.125f * LOG2E : 1.0f;

    const int wm = wid & 1;
    const int wn = wid >> 1;
    float acc[4][4][4];
    #pragma unroll
    for (int mt = 0; mt < 4; mt++)
        #pragma unroll
        for (int nt = 0; nt < 4; nt++)
            #pragma unroll
            for (int j = 0; j < 4; j++) acc[mt][nt][j] = 0.f;

    auto issue = [&](int chunk) {
        const int k0 = chunk * 64;
        const uint32_t base = sb + (uint32_t)(chunk & 1) * GB_SZ;
        #pragma unroll
        for (int i = 0; i < 8; i++) {
            const int q = i * 128 + tid;
            const int r = q >> 3, c = q & 7;
            const uint32_t sw = SWZ((uint32_t)(r * 128 + c * 16));
            const size_t go = (size_t)(m0 + r) * 512 + k0 + c * 8;
            cp16(base + GB_AH + sw, Ah + go);
            cp16(base + GB_AL + sw, Al + go);
        }
        #pragma unroll
        for (int i = 0; i < 4; i++) {
            const int q = i * 128 + tid;
            const int r = q >> 3, c = q & 7;
            const uint32_t sw = SWZ((uint32_t)(r * 128 + c * 16));
            const size_t go = (size_t)(n0 + r) * 512 + k0 + c * 8;
            cp16(base + GB_BH + sw, Bh + go);
            if (three) cp16(base + GB_BL + sw, Bl + go);
        }
        CP_COMMIT();
    };

    issue(0);

    const int a_row  = wm * 64 + (lane & 15);
    const int a_cofs = (lane >> 4) * 16;
    const int b_row  = wn * 32 + (lane & 7) + ((lane >> 4) << 3);
    const int b_cofs = ((lane >> 3) & 1) * 16;

    #pragma unroll 1
    for (int c = 0; c < 8; c++) {
        CP_WAIT0();
        __syncthreads();
        if (c < 7) issue(c + 1);
        const uint32_t base = sb + (uint32_t)(c & 1) * GB_SZ;

        #pragma unroll
        for (int ks = 0; ks < 4; ks++) {
            uint32_t ah[4][4], al[4][4], bh[2][4];
            #pragma unroll
            for (int mt = 0; mt < 4; mt++) {
                uint32_t sw = SWZ((uint32_t)((a_row + mt * 16) * 128 + ks * 32 + a_cofs));
                ldmatrix_x4(ah[mt], base + GB_AH + sw);
                ldmatrix_x4(al[mt], base + GB_AL + sw);
            }
            #pragma unroll
            for (int np = 0; np < 2; np++) {
                uint32_t sw = SWZ((uint32_t)((b_row + np * 16) * 128 + ks * 32 + b_cofs));
                ldmatrix_x4(bh[np], base + GB_BH + sw);
            }
            #pragma unroll
            for (int mt = 0; mt < 4; mt++)
                #pragma unroll
                for (int nt = 0; nt < 4; nt++)
                    mma_f16(acc[mt][nt], ah[mt], &bh[nt >> 1][(nt & 1) * 2]);
            #pragma unroll
            for (int mt = 0; mt < 4; mt++)
                #pragma unroll
                for (int nt = 0; nt < 4; nt++)
                    mma_f16(acc[mt][nt], al[mt], &bh[nt >> 1][(nt & 1) * 2]);
            if (three) {
                uint32_t bl[2][4];
                #pragma unroll
                for (int np = 0; np < 2; np++) {
                    uint32_t sw = SWZ((uint32_t)((b_row + np * 16) * 128 + ks * 32 + b_cofs));
                    ldmatrix_x4(bl[np], base + GB_BL + sw);
                }
                #pragma unroll
                for (int mt = 0; mt < 4; mt++)
                    #pragma unroll
                    for (int nt = 0; nt < 4; nt++)
                        mma_f16(acc[mt][nt], ah[mt], &bl[nt >> 1][(nt & 1) * 2]);
            }
        }
    }

    #pragma unroll
    for (int mt = 0; mt < 4; mt++) {
        const int r0 = m0 + wm * 64 + mt * 16 + (lane >> 2);
        #pragma unroll
        for (int nt = 0; nt < 4; nt++) {
            const int c0 = n0 + wn * 32 + nt * 8 + (lane & 3) * 2;
            float2 b = *(const float2*)(bias + c0);
            if (MODE == 0) {
                float2 v0 = make_float2(acc[mt][nt][0] + b.x, acc[mt][nt][1] + b.y);
                float2 v1 = make_float2(acc[mt][nt][2] + b.x, acc[mt][nt][3] + b.y);
                *(float2*)(C + (size_t)r0 * 512 + c0)       = v0;
                *(float2*)(C + (size_t)(r0 + 8) * 512 + c0) = v1;
            } else {
                int hh = c0 >> 6, d = c0 & 63;
                int bb = r0 >> 11, s = r0 & 2047;
                size_t base2 = ((size_t)z * MH) +
                               (((size_t)(bb * HEADS + hh)) * SEQ + s) * 64 + d;
                uint32_t hi, lo;
                split2h((acc[mt][nt][0] + b.x) * scale, (acc[mt][nt][1] + b.y) * scale, hi, lo);
                *(uint32_t*)(Oh + base2) = hi;
                *(uint32_t*)(Ol + base2) = lo;
                split2h((acc[mt][nt][2] + b.x) * scale, (acc[mt][nt][3] + b.y) * scale, hi, lo);
                *(uint32_t*)(Oh + base2 + 8 * 64) = hi;
                *(uint32_t*)(Ol + base2 + 8 * 64) = lo;
            }
        }
    }
}

// ===========================================================================
// fp16 flash attention v8: SPLIT-K x2. Each CTA covers 64 q-rows x 1024 keys.
// Static-max softmax makes partials additive: unnormalized O (fp32) and l
// written to global partial buffers; norm_split combines + splits to fp16.
// 3 CTAs/SM. QK 3-term (qh*kh + ql*kh + qh*kl). PV 1-term (ph*vh).
// smem: QH [0,8K) | QL [8K,16K) | buf{0,1} x (Kh|Kl|Vh 8K) [16K,64K)
//       | maskbias 1024 f32 [64K,68K)
// ===========================================================================
constexpr int ATT_SMEM = 69632;
constexpr int KV0      = 16384;
constexpr int KVSZ     = 24576;
constexpr int MBIAS    = 65536;
constexpr int KSPLIT   = SEQ / 2;    // 1024 keys per split
constexpr int NT       = KSPLIT / 64;  // 16 tiles

__global__ __launch_bounds__(128, 3)
void attn_mma(const __half* __restrict__ Hh, const __half* __restrict__ Hl,
              const int* __restrict__ mask,
              float* __restrict__ Po, float* __restrict__ Pl)
{
    extern __shared__ __align__(1024) char sm[];
    const uint32_t sb = smem_u32(sm);
    const int tid  = threadIdx.x;
    const int wid  = tid >> 5;
    const int lane = tid & 31;
    const int qb = blockIdx.x >> 1;
    const int s  = blockIdx.x & 1;
    const int h = blockIdx.y, b = blockIdx.z;
    const int bh = b * HEADS + h;
    const int K0 = s * KSPLIT;

    const __half* Qhp = Hh + 0 * (size_t)MH + ((size_t)bh * SEQ + qb * 64) * 64;
    const __half* Qlp = Hl + 0 * (size_t)MH + ((size_t)bh * SEQ + qb * 64) * 64;
    const __half* Khp = Hh + 1 * (size_t)MH + ((size_t)bh * SEQ + K0) * 64;
    const __half* Klp = Hl + 1 * (size_t)MH + ((size_t)bh * SEQ + K0) * 64;
    const __half* Vhp = Hh + 2 * (size_t)MH + ((size_t)bh * SEQ + K0) * 64;
    const int* mb = mask + b * SEQ + K0;

    auto issue_kv = [&](int t) {
        const uint32_t dst0 = sb + KV0 + (uint32_t)(t & 1) * KVSZ;
        #pragma unroll
        for (int i = 0; i < 12; i++) {
            const int f   = i * 128 + tid;
            const int buf = i >> 2;                 // 0=Kh, 1=Kl, 2=Vh
            const int r   = (f >> 3) & 63;
            const int c   = f & 7;
            const __half* src = (buf == 0) ? Khp : (buf == 1) ? Klp : Vhp;
            cp16(dst0 + buf * 8192 + SWZ((uint32_t)(r * 128 + c * 16)),
                 src + (size_t)(t * 64 + r) * 64 + c * 8);
        }
        CP_COMMIT();
    };

    issue_kv(0);

    // stage Q (64 rows x 64 fp16 hi/lo) — stays resident all kernel
    {
        const int row = tid >> 1, half = tid & 1;
        const uint4* shp = (const uint4*)(Qhp + row * 64 + half * 32);
        const uint4* slp = (const uint4*)(Qlp + row * 64 + half * 32);
        #pragma unroll
        for (int i = 0; i < 4; i++) {
            uint32_t sw = SWZ((uint32_t)(row * 128 + half * 64 + i * 16));
            *(uint4*)(sm + sw)        = shp[i];
            *(uint4*)(sm + 8192 + sw) = slp[i];
        }
    }
    // mask (this split's half) -> log2-domain additive bias
    for (int i = tid; i < KSPLIT; i += 128)
        *(float*)(sm + MBIAS + i * 4) = mb[i] ? -SHIFT2 : -1e9f;

    CP_WAIT0();
    __syncthreads();
    issue_kv(1);

    float O[8][4];
    #pragma unroll
    for (int dc = 0; dc < 8; dc++)
        #pragma unroll
        for (int j = 0; j < 4; j++) O[dc][j] = 0.f;
    float l0 = 0.f, l1 = 0.f;

    const int arow = wid * 16 + (lane & 15);
    const int acol = (lane >> 4) * 16;
    const int krow = (lane & 7) + ((lane >> 4) << 3);
    const int kcol = ((lane >> 3) & 1) * 16;
    const int vrow = (lane & 15);
    const int vcol = ((lane >> 4) & 1) * 16;
    const uint32_t ones2[2] = {0x3C003C00u, 0x3C003C00u};

    #pragma unroll 1
    for (int t = 0; t < NT; t++) {
        const uint32_t kv = sb + KV0 + (uint32_t)(t & 1) * KVSZ;

        // ==== S' = Q @ K^T (3-term: qh*kh + ql*kh + qh*kl) ====
        float S[8][4];
        #pragma unroll
        for (int nc = 0; nc < 8; nc++)
            #pragma unroll
            for (int j = 0; j < 4; j++) S[nc][j] = 0.f;

        #pragma unroll
        for (int ks = 0; ks < 4; ks++) {
            uint32_t qfh[4], qfl[4], kh[4][4], kl[4][4];
            {
                uint32_t sw = SWZ((uint32_t)(arow * 128 + ks * 32 + acol));
                ldmatrix_x4(qfh, sb + sw);
                ldmatrix_x4(qfl, sb + 8192 + sw);
            }
            #pragma unroll
            for (int np = 0; np < 4; np++) {
                uint32_t sw = SWZ((uint32_t)((np * 16 + krow) * 128 + ks * 32 + kcol));
                ldmatrix_x4(kh[np], kv + sw);
                ldmatrix_x4(kl[np], kv + 8192 + sw);
            }
            #pragma unroll
            for (int np = 0; np < 4; np++)
                #pragma unroll
                for (int sub = 0; sub < 2; sub++)
                    mma_f16(S[np * 2 + sub], qfh, &kh[np][sub * 2]);
            #pragma unroll
            for (int np = 0; np < 4; np++)
                #pragma unroll
                for (int sub = 0; sub < 2; sub++)
                    mma_f16(S[np * 2 + sub], qfl, &kh[np][sub * 2]);
            #pragma unroll
            for (int np = 0; np < 4; np++)
                #pragma unroll
                for (int sub = 0; sub < 2; sub++)
                    mma_f16(S[np * 2 + sub], qfh, &kl[np][sub * 2]);
        }

        // ==== P = 2^(S' + bias') via ex2.approx.f16x2 ====
        uint32_t ph[4][4];
        #pragma unroll
        for (int kc = 0; kc < 4; kc++) {
            #pragma unroll
            for (int sub = 0; sub < 2; sub++) {
                const int nc = kc * 2 + sub;
                float2 bb = *(const float2*)(sm + MBIAS +
                                             (t * 64 + nc * 8 + 2 * (lane & 3)) * 4);
                float d0 = S[nc][0] + bb.x, d1 = S[nc][1] + bb.y;
                float d2 = S[nc][2] + bb.x, d3 = S[nc][3] + bb.y;
                ph[kc][sub * 2]     = exp2_f16x2(cvt_f16x2(d1, d0));
                ph[kc][sub * 2 + 1] = exp2_f16x2(cvt_f16x2(d3, d2));
            }
        }

        // ==== l-tile via P @ ones ====
        float Lt[4] = {0.f, 0.f, 0.f, 0.f};
        #pragma unroll
        for (int kc = 0; kc < 4; kc++)
            mma_f16(Lt, ph[kc], ones2);

        // ==== O += P @ Vh ====
        #pragma unroll
        for (int kc = 0; kc < 4; kc++) {
            uint32_t vh[4][4];
            #pragma unroll
            for (int dp = 0; dp < 4; dp++) {
                uint32_t sw = SWZ((uint32_t)((kc * 16 + vrow) * 128 + dp * 32 + vcol));
                ldmatrix_x4_t(vh[dp], kv + 16384 + sw);
            }
            #pragma unroll
            for (int dp = 0; dp < 4; dp++)
                #pragma unroll
                for (int sub = 0; sub < 2; sub++)
                    mma_f16(O[dp * 2 + sub], ph[kc], &vh[dp][sub * 2]);
        }

        l0 += Lt[0];
        l1 += Lt[2];

        if (t < NT - 1) {
            CP_WAIT0();
            __syncthreads();
            if (t < NT - 2) issue_kv(t + 2);
        }
    }

    // ==== write unnormalized partials (fp32) ====
    const int qrow = qb * 64 + wid * 16 + (lane >> 2);
    float* po = Po + (((size_t)(s * BH + bh)) * SEQ + qrow) * 64 + (lane & 3) * 2;
    #pragma unroll
    for (int dc = 0; dc < 8; dc++) {
        *(float2*)(po + dc * 8)            = make_float2(O[dc][0], O[dc][1]);
        *(float2*)(po + 8 * 64 + dc * 8)   = make_float2(O[dc][2], O[dc][3]);
    }
    if ((lane & 3) == 0) {
        Pl[((size_t)(s * BH + bh)) * SEQ + qrow]     = l0;
        Pl[((size_t)(s * BH + bh)) * SEQ + qrow + 8] = l1;
    }
}

// ===========================================================================
// Combine split-K partials, normalize, split to fp16 hi/lo ctx [token][512]
// ===========================================================================
__global__ void norm_split(const float* __restrict__ Po, const float* __restrict__ Pl,
                           __half* __restrict__ Ch, __half* __restrict__ Cl)
{
    int r = blockIdx.x * blockDim.x + threadIdx.x;   // 0 .. BH*SEQ-1
    int bh = r >> 11, srow = r & 2047;
    const float* p0 = Po + ((size_t)bh * SEQ + srow) * 64;
    const float* p1 = p0 + (size_t)BH * SEQ * 64;
    float l = Pl[(size_t)bh * SEQ + srow] + Pl[(size_t)BH * SEQ + bh * SEQ + srow];
    float inv = 1.f / l;
    int b = bh >> 3, h = bh & 7;
    size_t dst = ((size_t)(b * SEQ + srow)) * 512 + h * 64;
    #pragma unroll
    for (int c = 0; c < 64; c += 8) {
        float4 a0 = *(const float4*)(p0 + c);
        float4 a1 = *(const float4*)(p1 + c);
        float4 b0 = *(const float4*)(p0 + c + 4);
        float4 b1 = *(const float4*)(p1 + c + 4);
        uint32_t hi, lo;
        split2h((a0.x + a1.x) * inv, (a0.y + a1.y) * inv, hi, lo);
        *(uint32_t*)(Ch + dst + c)     = hi;
        *(uint32_t*)(Cl + dst + c)     = lo;
        split2h((a0.z + a1.z) * inv, (a0.w + a1.w) * inv, hi, lo);
        *(uint32_t*)(Ch + dst + c + 2) = hi;
        *(uint32_t*)(Cl + dst + c + 2) = lo;
        split2h((b0.x + b1.x) * inv, (b0.y + b1.y) * inv, hi, lo);
        *(uint32_t*)(Ch + dst + c + 4) = hi;
        *(uint32_t*)(Cl + dst + c + 4) = lo;
        split2h((b0.z + b1.z) * inv, (b0.w + b1.w) * inv, hi, lo);
        *(uint32_t*)(Ch + dst + c + 6) = hi;
        *(uint32_t*)(Cl + dst + c + 6) = lo;
    }
}

// ---------------------------------------------------------------------------
// Launch
// ---------------------------------------------------------------------------
extern "C" void kernel_launch(void* const* d_in, const int* in_sizes, int n_in,
                              void* d_out, int out_size)
{
    const float* values = (const float*)d_in[0];
    const float* keys   = (const float*)d_in[1];
    const float* query  = (const float*)d_in[2];
    const int*   mask   = (const int*)d_in[3];
    const float* Wq = (const float*)d_in[4];
    const float* bq = (const float*)d_in[5];
    const float* Wk = (const float*)d_in[6];
    const float* bk = (const float*)d_in[7];
    const float* Wv = (const float*)d_in[8];
    const float* bv = (const float*)d_in[9];
    const float* Wo = (const float*)d_in[10];
    const float* bo = (const float*)d_in[11];
    float* out = (float*)d_out;

    __half *wth, *wtl, *sh, *sl, *ch, *cl, *hh, *hl;
    float *po, *pl;
    cudaGetSymbolAddress((void**)&wth, g_Wth);
    cudaGetSymbolAddress((void**)&wtl, g_Wtl);
    cudaGetSymbolAddress((void**)&sh,  g_Sh);
    cudaGetSymbolAddress((void**)&sl,  g_Sl);
    cudaGetSymbolAddress((void**)&hh,  g_Hh);
    cudaGetSymbolAddress((void**)&hl,  g_Hl);
    cudaGetSymbolAddress((void**)&ch,  g_Ch);
    cudaGetSymbolAddress((void**)&cl,  g_Cl);
    cudaGetSymbolAddress((void**)&po,  g_Po);
    cudaGetSymbolAddress((void**)&pl,  g_Pl);

    cudaFuncSetAttribute(gemm_v4<0>, cudaFuncAttributeMaxDynamicSharedMemorySize, GEMM_SMEM);
    cudaFuncSetAttribute(gemm_v4<1>, cudaFuncAttributeMaxDynamicSharedMemorySize, GEMM_SMEM);
    cudaFuncSetAttribute(attn_mma,   cudaFuncAttributeMaxDynamicSharedMemorySize, ATT_SMEM);

    prep_weights<<<4 * HID * HID / 256, 256>>>(Wq, Wk, Wv, Wo, wth, wtl);
    prep_acts<<<3 * MH / 4 / 256, 256>>>(query, keys, values, sh, sl);

    dim3 gqkv(HID / 64, MROWS / 128, 3);    // (8, 64, 3) = 1536 CTAs, 2/SM
    gemm_v4<1><<<gqkv, 128, GEMM_SMEM>>>(sh, sl, wth, wtl, bq, bk, bv,
                                         nullptr, hh, hl);

    dim3 agrid(2 * SEQ / 64, HEADS, BATCH); // (64, 8, 4) = 2048 CTAs (split-K x2), 3/SM
    attn_mma<<<agrid, 128, ATT_SMEM>>>(hh, hl, mask, po, pl);

    norm_split<<<BH * SEQ / 128, 128>>>(po, pl, ch, cl);

    dim3 gout(HID / 64, MROWS / 128);       // (8, 64) = 512 CTAs, 2/SM
    gemm_v4<0><<<gout, 128, GEMM_SMEM>>>(ch, cl, wth + 3 * HID * HID, wtl + 3 * HID * HID,
                                         bo, nullptr, nullptr, out, nullptr, nullptr);
}

// round 14
// speedup vs baseline: 1.3842x; 1.3842x over previous
#include <cuda_runtime.h>
#include <cuda_bf16.h>
#include <cuda_fp16.h>
#include <cstdint>

// Problem constants
constexpr int BATCH = 4;
constexpr int SEQ   = 2048;
constexpr int HID   = 512;
constexpr int HEADS = 8;
constexpr int HDIM  = 64;
constexpr int MROWS = BATCH * SEQ;           // 8192
constexpr int MH    = MROWS * HID;           // 4194304
constexpr int BH    = BATCH * HEADS;         // 32

// Scratch (device globals; no allocation allowed)
__device__ __half g_Sh[3 * MH];   // split activations (GEMM A, fp16 hi): [z][token][512]
__device__ __half g_Sl[3 * MH];   // fp16 lo residuals
__device__ __half g_Hh[3 * MH];   // head-layout Q/K/V fp16 hi: [z][b*8+h][s][64]
__device__ __half g_Hl[3 * MH];   // fp16 lo (used for Q and K)
__device__ __half g_Ch[MH];       // split ctx: [token][512]
__device__ __half g_Cl[MH];
__device__ __half g_Wth[4 * HID * HID];   // Wt fp16 hi
__device__ __half g_Wtl[4 * HID * HID];   // Wt fp16 lo
// Mask compaction: per-batch unmasked key indices + compacted K/V + bias
__device__ int    g_Idx[BATCH * SEQ];
__device__ int    g_NB[BATCH];            // unmasked count
__device__ int    g_NT[BATCH];            // padded tile count (npad/64)
__device__ float  g_Bc[BATCH * SEQ];      // compacted log2-bias (-SHIFT2 / -1e9 pad)
__device__ __half g_Kch[BH * SEQ * HDIM]; // compacted K hi per bh
__device__ __half g_Kcl[BH * SEQ * HDIM]; // compacted K lo
__device__ __half g_Vch[BH * SEQ * HDIM]; // compacted V hi

#define SWZ(o) ((o) ^ (((o) >> 3) & 0x70))

__device__ __forceinline__ uint32_t smem_u32(const void* p) {
    uint32_t a;
    asm("{ .reg .u64 t; cvta.to.shared.u64 t, %1; cvt.u32.u64 %0, t; }" : "=r"(a) : "l"(p));
    return a;
}
// fp16 split: value = hi + lo to ~2^-22
__device__ __forceinline__ void split2h(float a, float b, uint32_t& hi, uint32_t& lo) {
    __half2 h = __floats2half2_rn(a, b);
    float ra = a - __half2float(__low2half(h));
    float rb = b - __half2float(__high2half(h));
    hi = *reinterpret_cast<uint32_t*>(&h);
    __half2 l = __floats2half2_rn(ra, rb);
    lo = *reinterpret_cast<uint32_t*>(&l);
}
// d = {lo: lo_src, hi: hi_src}
__device__ __forceinline__ uint32_t cvt_f16x2(float hi_src, float lo_src) {
    uint32_t d;
    asm("cvt.rn.f16x2.f32 %0, %1, %2;" : "=r"(d) : "f"(hi_src), "f"(lo_src));
    return d;
}
__device__ __forceinline__ uint32_t exp2_f16x2(uint32_t x) {
    uint32_t d;
    asm("ex2.approx.f16x2 %0, %1;" : "=r"(d) : "r"(x));
    return d;
}
__device__ __forceinline__ void ldmatrix_x4(uint32_t* r, uint32_t addr) {
    asm volatile("ldmatrix.sync.aligned.m8n8.x4.shared.b16 {%0,%1,%2,%3}, [%4];"
                 : "=r"(r[0]), "=r"(r[1]), "=r"(r[2]), "=r"(r[3]) : "r"(addr));
}
__device__ __forceinline__ void ldmatrix_x4_t(uint32_t* r, uint32_t addr) {
    asm volatile("ldmatrix.sync.aligned.m8n8.x4.trans.shared.b16 {%0,%1,%2,%3}, [%4];"
                 : "=r"(r[0]), "=r"(r[1]), "=r"(r[2]), "=r"(r[3]) : "r"(addr));
}
__device__ __forceinline__ void mma_f16(float* d, const uint32_t* a, const uint32_t* b) {
    asm volatile("mma.sync.aligned.m16n8k16.row.col.f32.f16.f16.f32 "
                 "{%0,%1,%2,%3}, {%4,%5,%6,%7}, {%8,%9}, {%0,%1,%2,%3};"
                 : "+f"(d[0]), "+f"(d[1]), "+f"(d[2]), "+f"(d[3])
                 : "r"(a[0]), "r"(a[1]), "r"(a[2]), "r"(a[3]), "r"(b[0]), "r"(b[1]));
}
__device__ __forceinline__ void cp16(uint32_t s, const void* g) {
    asm volatile("cp.async.cg.shared.global [%0], [%1], 16;" :: "r"(s), "l"(g));
}
#define CP_COMMIT() asm volatile("cp.async.commit_group;" ::: "memory")
#define CP_WAIT0()  asm volatile("cp.async.wait_group 0;" ::: "memory")

// Static softmax shift (log2 domain). p = 2^(S' - SHIFT2), S' = log2e * S.
constexpr float SHIFT2 = 6.0f;
constexpr float LOG2E  = 1.4426950408889634f;

// ===========================================================================
// Prep kernels (fp16 hi/lo splits)
// ===========================================================================
__global__ void prep_weights(const float* __restrict__ Wq, const float* __restrict__ Wk,
                             const float* __restrict__ Wv, const float* __restrict__ Wo,
                             __half* __restrict__ Wth, __half* __restrict__ Wtl)
{
    int idx = blockIdx.x * blockDim.x + threadIdx.x;
    int mat = idx >> 18;
    int r   = idx & 262143;
    int n   = r >> 9;
    int k   = r & 511;
    const float* W = (mat == 0) ? Wq : (mat == 1) ? Wk : (mat == 2) ? Wv : Wo;
    float w  = W[k * 512 + n];
    __half hi = __float2half_rn(w);
    float lo = w - __half2float(hi);
    Wth[idx] = hi;
    Wtl[idx] = __float2half_rn(lo);
}

__global__ void prep_acts(const float* __restrict__ q, const float* __restrict__ k,
                          const float* __restrict__ v,
                          __half* __restrict__ Sh, __half* __restrict__ Sl)
{
    int i = blockIdx.x * blockDim.x + threadIdx.x;   // float4 units
    const int per = MH / 4;
    int z = i / per, r = i - z * per;
    const float* src = (z == 0) ? q : (z == 1) ? k : v;
    float4 x = ((const float4*)src)[r];
    uint32_t h0, l0, h1, l1;
    split2h(x.x, x.y, h0, l0);
    split2h(x.z, x.w, h1, l1);
    ((uint2*)Sh)[i] = make_uint2(h0, h1);
    ((uint2*)Sl)[i] = make_uint2(l0, l1);
}

// ===========================================================================
// Mask scan: per batch, prefix-sum mask -> compacted index list + counts +
// compacted log2-domain bias (pad region gets -1e9 -> p = 0 exactly).
// ===========================================================================
__global__ void scan_mask(const int* __restrict__ mask, int* __restrict__ idx,
                          int* __restrict__ nbarr, int* __restrict__ ntarr,
                          float* __restrict__ biasc)
{
    __shared__ int ps[256];
    __shared__ int nb_sh;
    const int b = blockIdx.x, tid = threadIdx.x;
    const int* mb = mask + b * SEQ;
    int loc[8], s = 0;
    #pragma unroll
    for (int i = 0; i < 8; i++) { loc[i] = mb[tid * 8 + i]; s += loc[i]; }
    ps[tid] = s;
    __syncthreads();
    // Hillis-Steele inclusive scan (256 entries)
    for (int d = 1; d < 256; d <<= 1) {
        int v = (tid >= d) ? ps[tid - d] : 0;
        __syncthreads();
        ps[tid] += v;
        __syncthreads();
    }
    int base = ps[tid] - s;            // exclusive prefix
    if (tid == 255) nb_sh = ps[255];
    __syncthreads();
    #pragma unroll
    for (int i = 0; i < 8; i++)
        if (loc[i]) idx[b * SEQ + base++] = tid * 8 + i;
    const int nb   = nb_sh;
    const int npad = (nb + 63) & ~63;
    for (int j = tid; j < SEQ; j += 256)
        biasc[b * SEQ + j] = (j < nb) ? -SHIFT2 : -1e9f;
    if (tid == 0) { nbarr[b] = nb; ntarr[b] = npad >> 6; }
}

// ===========================================================================
// Gather compacted K/V head-layout buffers (runs after QKV GEMM).
// blockIdx.y selects buffer: 0=Kh, 1=Kl, 2=Vh. Pad rows zero-filled.
// ===========================================================================
__global__ void gather_kv(const __half* __restrict__ Hh, const __half* __restrict__ Hl,
                          const int* __restrict__ idx, const int* __restrict__ nbarr,
                          const int* __restrict__ ntarr,
                          __half* __restrict__ Kch, __half* __restrict__ Kcl,
                          __half* __restrict__ Vch)
{
    int g  = blockIdx.x * 256 + threadIdx.x;   // (bh*2048 + j)*8 + c
    int c  = g & 7;
    int j  = (g >> 3) & 2047;
    int bh = g >> 14;
    int b  = bh >> 3;
    int buf = blockIdx.y;
    int nb   = __ldg(&nbarr[b]);
    int npad = __ldg(&ntarr[b]) * 64;
    if (j >= npad) return;
    uint4 val = make_uint4(0u, 0u, 0u, 0u);
    if (j < nb) {
        int srow = __ldg(&idx[b * SEQ + j]);
        const __half* src = ((buf == 0) ? (Hh + (size_t)MH) :
                             (buf == 1) ? (Hl + (size_t)MH) :
                                          (Hh + 2 * (size_t)MH))
                            + ((size_t)bh * SEQ + srow) * 64 + c * 8;
        val = *(const uint4*)src;
    }
    __half* dst = ((buf == 0) ? Kch : (buf == 1) ? Kcl : Vch)
                  + ((size_t)bh * SEQ + j) * 64 + c * 8;
    *(uint4*)dst = val;
}

// ===========================================================================
// HMMA fp16 GEMM v4 (unchanged from R12): CTA 128x64, 4 warps, 2 CTAs/SM.
// ===========================================================================
constexpr int GB_AH = 0;
constexpr int GB_AL = 16384;
constexpr int GB_BH = 32768;
constexpr int GB_BL = 40960;
constexpr int GB_SZ = 49152;
constexpr int GEMM_SMEM = 98304;

template<int MODE>
__global__ __launch_bounds__(128, 2)
void gemm_v4(const __half* __restrict__ Ah_, const __half* __restrict__ Al_,
             const __half* __restrict__ Bh_, const __half* __restrict__ Bl_,
             const float* __restrict__ b0, const float* __restrict__ b1,
             const float* __restrict__ b2,
             float* __restrict__ C, __half* __restrict__ Oh, __half* __restrict__ Ol)
{
    extern __shared__ __align__(1024) char smem[];
    const uint32_t sb = smem_u32(smem);
    const int tid = threadIdx.x, wid = tid >> 5, lane = tid & 31;
    const int n0 = blockIdx.x * 64, m0 = blockIdx.y * 128;
    const int z  = (MODE == 1) ? blockIdx.z : 0;
    const bool three = (MODE == 1) && (z != 2);

    const __half* Ah = Ah_ + (size_t)z * MH;
    const __half* Al = Al_ + (size_t)z * MH;
    const __half* Bh = Bh_ + (size_t)z * HID * HID;
    const __half* Bl = Bl_ + (size_t)z * HID * HID;
    const float* bias = (z == 0) ? b0 : (z == 1) ? b1 : b2;
    const float scale = (MODE == 1 && z == 0) ? 0.125f * LOG2E : 1.0f;

    const int wm = wid & 1;
    const int wn = wid >> 1;
    float acc[4][4][4];
    #pragma unroll
    for (int mt = 0; mt < 4; mt++)
        #pragma unroll
        for (int nt = 0; nt < 4; nt++)
            #pragma unroll
            for (int j = 0; j < 4; j++) acc[mt][nt][j] = 0.f;

    auto issue = [&](int chunk) {
        const int k0 = chunk * 64;
        const uint32_t base = sb + (uint32_t)(chunk & 1) * GB_SZ;
        #pragma unroll
        for (int i = 0; i < 8; i++) {
            const int q = i * 128 + tid;
            const int r = q >> 3, c = q & 7;
            const uint32_t sw = SWZ((uint32_t)(r * 128 + c * 16));
            const size_t go = (size_t)(m0 + r) * 512 + k0 + c * 8;
            cp16(base + GB_AH + sw, Ah + go);
            cp16(base + GB_AL + sw, Al + go);
        }
        #pragma unroll
        for (int i = 0; i < 4; i++) {
            const int q = i * 128 + tid;
            const int r = q >> 3, c = q & 7;
            const uint32_t sw = SWZ((uint32_t)(r * 128 + c * 16));
            const size_t go = (size_t)(n0 + r) * 512 + k0 + c * 8;
            cp16(base + GB_BH + sw, Bh + go);
            if (three) cp16(base + GB_BL + sw, Bl + go);
        }
        CP_COMMIT();
    };

    issue(0);

    const int a_row  = wm * 64 + (lane & 15);
    const int a_cofs = (lane >> 4) * 16;
    const int b_row  = wn * 32 + (lane & 7) + ((lane >> 4) << 3);
    const int b_cofs = ((lane >> 3) & 1) * 16;

    #pragma unroll 1
    for (int c = 0; c < 8; c++) {
        CP_WAIT0();
        __syncthreads();
        if (c < 7) issue(c + 1);
        const uint32_t base = sb + (uint32_t)(c & 1) * GB_SZ;

        #pragma unroll
        for (int ks = 0; ks < 4; ks++) {
            uint32_t ah[4][4], al[4][4], bh[2][4];
            #pragma unroll
            for (int mt = 0; mt < 4; mt++) {
                uint32_t sw = SWZ((uint32_t)((a_row + mt * 16) * 128 + ks * 32 + a_cofs));
                ldmatrix_x4(ah[mt], base + GB_AH + sw);
                ldmatrix_x4(al[mt], base + GB_AL + sw);
            }
            #pragma unroll
            for (int np = 0; np < 2; np++) {
                uint32_t sw = SWZ((uint32_t)((b_row + np * 16) * 128 + ks * 32 + b_cofs));
                ldmatrix_x4(bh[np], base + GB_BH + sw);
            }
            #pragma unroll
            for (int mt = 0; mt < 4; mt++)
                #pragma unroll
                for (int nt = 0; nt < 4; nt++)
                    mma_f16(acc[mt][nt], ah[mt], &bh[nt >> 1][(nt & 1) * 2]);
            #pragma unroll
            for (int mt = 0; mt < 4; mt++)
                #pragma unroll
                for (int nt = 0; nt < 4; nt++)
                    mma_f16(acc[mt][nt], al[mt], &bh[nt >> 1][(nt & 1) * 2]);
            if (three) {
                uint32_t bl[2][4];
                #pragma unroll
                for (int np = 0; np < 2; np++) {
                    uint32_t sw = SWZ((uint32_t)((b_row + np * 16) * 128 + ks * 32 + b_cofs));
                    ldmatrix_x4(bl[np], base + GB_BL + sw);
                }
                #pragma unroll
                for (int mt = 0; mt < 4; mt++)
                    #pragma unroll
                    for (int nt = 0; nt < 4; nt++)
                        mma_f16(acc[mt][nt], ah[mt], &bl[nt >> 1][(nt & 1) * 2]);
            }
        }
    }

    #pragma unroll
    for (int mt = 0; mt < 4; mt++) {
        const int r0 = m0 + wm * 64 + mt * 16 + (lane >> 2);
        #pragma unroll
        for (int nt = 0; nt < 4; nt++) {
            const int c0 = n0 + wn * 32 + nt * 8 + (lane & 3) * 2;
            float2 b = *(const float2*)(bias + c0);
            if (MODE == 0) {
                float2 v0 = make_float2(acc[mt][nt][0] + b.x, acc[mt][nt][1] + b.y);
                float2 v1 = make_float2(acc[mt][nt][2] + b.x, acc[mt][nt][3] + b.y);
                *(float2*)(C + (size_t)r0 * 512 + c0)       = v0;
                *(float2*)(C + (size_t)(r0 + 8) * 512 + c0) = v1;
            } else {
                int hh = c0 >> 6, d = c0 & 63;
                int bb = r0 >> 11, s = r0 & 2047;
                size_t base2 = ((size_t)z * MH) +
                               (((size_t)(bb * HEADS + hh)) * SEQ + s) * 64 + d;
                uint32_t hi, lo;
                split2h((acc[mt][nt][0] + b.x) * scale, (acc[mt][nt][1] + b.y) * scale, hi, lo);
                *(uint32_t*)(Oh + base2) = hi;
                *(uint32_t*)(Ol + base2) = lo;
                split2h((acc[mt][nt][2] + b.x) * scale, (acc[mt][nt][3] + b.y) * scale, hi, lo);
                *(uint32_t*)(Oh + base2 + 8 * 64) = hi;
                *(uint32_t*)(Ol + base2 + 8 * 64) = lo;
            }
        }
    }
}

// ===========================================================================
// fp16 flash attention v9: mask-compacted keys. Each CTA: 64 q rows x
// nt[b]*64 compacted keys (~half of SEQ). Static-max softmax (log2 domain),
// 3 CTAs/SM. QK 3-term (qh*kh + ql*kh + qh*kl). PV 1-term (ph*vh).
// Compacted pad keys carry bias -1e9 -> p = 0 exactly.
// smem: QH [0,8K) | QL [8K,16K) | buf{0,1} x (Kh|Kl|Vh 8K) [16K,64K)
//       | compacted bias <=2048 f32 [64K,72K)
// ===========================================================================
constexpr int ATT_SMEM = 73728;
constexpr int KV0      = 16384;
constexpr int KVSZ     = 24576;
constexpr int MBIAS    = 65536;

__global__ __launch_bounds__(128, 3)
void attn_mma(const __half* __restrict__ Hh, const __half* __restrict__ Hl,
              const __half* __restrict__ Kch, const __half* __restrict__ Kcl,
              const __half* __restrict__ Vch,
              const float* __restrict__ biasc, const int* __restrict__ ntarr,
              __half* __restrict__ Ch, __half* __restrict__ Cl)
{
    extern __shared__ __align__(1024) char sm[];
    const uint32_t sb = smem_u32(sm);
    const int tid  = threadIdx.x;
    const int wid  = tid >> 5;
    const int lane = tid & 31;
    const int qb = blockIdx.x, h = blockIdx.y, b = blockIdx.z;
    const int bh = b * HEADS + h;
    const int nt = __ldg(&ntarr[b]);

    const __half* Qhp = Hh + 0 * (size_t)MH + ((size_t)bh * SEQ + qb * 64) * 64;
    const __half* Qlp = Hl + 0 * (size_t)MH + ((size_t)bh * SEQ + qb * 64) * 64;
    const __half* Khp = Kch + (size_t)bh * SEQ * 64;
    const __half* Klp = Kcl + (size_t)bh * SEQ * 64;
    const __half* Vhp = Vch + (size_t)bh * SEQ * 64;

    auto issue_kv = [&](int t) {
        const uint32_t dst0 = sb + KV0 + (uint32_t)(t & 1) * KVSZ;
        #pragma unroll
        for (int i = 0; i < 12; i++) {
            const int f   = i * 128 + tid;
            const int buf = i >> 2;                 // 0=Kh, 1=Kl, 2=Vh
            const int r   = (f >> 3) & 63;
            const int c   = f & 7;
            const __half* src = (buf == 0) ? Khp : (buf == 1) ? Klp : Vhp;
            cp16(dst0 + buf * 8192 + SWZ((uint32_t)(r * 128 + c * 16)),
                 src + (size_t)(t * 64 + r) * 64 + c * 8);
        }
        CP_COMMIT();
    };

    issue_kv(0);

    // stage Q (64 rows x 64 fp16 hi/lo) — stays resident all kernel
    {
        const int row = tid >> 1, half = tid & 1;
        const uint4* shp = (const uint4*)(Qhp + row * 64 + half * 32);
        const uint4* slp = (const uint4*)(Qlp + row * 64 + half * 32);
        #pragma unroll
        for (int i = 0; i < 4; i++) {
            uint32_t sw = SWZ((uint32_t)(row * 128 + half * 64 + i * 16));
            *(uint4*)(sm + sw)        = shp[i];
            *(uint4*)(sm + 8192 + sw) = slp[i];
        }
    }
    // compacted bias (covers nt*64 keys, includes -1e9 padding markers)
    for (int i = tid; i < nt * 64; i += 128)
        *(float*)(sm + MBIAS + i * 4) = __ldg(&biasc[b * SEQ + i]);

    CP_WAIT0();
    __syncthreads();
    issue_kv(1);

    float O[8][4];
    #pragma unroll
    for (int dc = 0; dc < 8; dc++)
        #pragma unroll
        for (int j = 0; j < 4; j++) O[dc][j] = 0.f;
    float l0 = 0.f, l1 = 0.f;

    const int arow = wid * 16 + (lane & 15);
    const int acol = (lane >> 4) * 16;
    const int krow = (lane & 7) + ((lane >> 4) << 3);
    const int kcol = ((lane >> 3) & 1) * 16;
    const int vrow = (lane & 15);
    const int vcol = ((lane >> 4) & 1) * 16;
    const uint32_t ones2[2] = {0x3C003C00u, 0x3C003C00u};

    #pragma unroll 1
    for (int t = 0; t < nt; t++) {
        const uint32_t kv = sb + KV0 + (uint32_t)(t & 1) * KVSZ;

        // ==== S' = Q @ K^T (3-term: qh*kh + ql*kh + qh*kl) ====
        float S[8][4];
        #pragma unroll
        for (int nc = 0; nc < 8; nc++)
            #pragma unroll
            for (int j = 0; j < 4; j++) S[nc][j] = 0.f;

        #pragma unroll
        for (int ks = 0; ks < 4; ks++) {
            uint32_t qfh[4], qfl[4], kh[4][4], kl[4][4];
            {
                uint32_t sw = SWZ((uint32_t)(arow * 128 + ks * 32 + acol));
                ldmatrix_x4(qfh, sb + sw);
                ldmatrix_x4(qfl, sb + 8192 + sw);
            }
            #pragma unroll
            for (int np = 0; np < 4; np++) {
                uint32_t sw = SWZ((uint32_t)((np * 16 + krow) * 128 + ks * 32 + kcol));
                ldmatrix_x4(kh[np], kv + sw);
                ldmatrix_x4(kl[np], kv + 8192 + sw);
            }
            #pragma unroll
            for (int np = 0; np < 4; np++)
                #pragma unroll
                for (int sub = 0; sub < 2; sub++)
                    mma_f16(S[np * 2 + sub], qfh, &kh[np][sub * 2]);
            #pragma unroll
            for (int np = 0; np < 4; np++)
                #pragma unroll
                for (int sub = 0; sub < 2; sub++)
                    mma_f16(S[np * 2 + sub], qfl, &kh[np][sub * 2]);
            #pragma unroll
            for (int np = 0; np < 4; np++)
                #pragma unroll
                for (int sub = 0; sub < 2; sub++)
                    mma_f16(S[np * 2 + sub], qfh, &kl[np][sub * 2]);
        }

        // ==== P = 2^(S' + bias') via ex2.approx.f16x2 ====
        uint32_t ph[4][4];
        #pragma unroll
        for (int kc = 0; kc < 4; kc++) {
            #pragma unroll
            for (int sub = 0; sub < 2; sub++) {
                const int nc = kc * 2 + sub;
                float2 bb = *(const float2*)(sm + MBIAS +
                                             (t * 64 + nc * 8 + 2 * (lane & 3)) * 4);
                float d0 = S[nc][0] + bb.x, d1 = S[nc][1] + bb.y;
                float d2 = S[nc][2] + bb.x, d3 = S[nc][3] + bb.y;
                ph[kc][sub * 2]     = exp2_f16x2(cvt_f16x2(d1, d0));
                ph[kc][sub * 2 + 1] = exp2_f16x2(cvt_f16x2(d3, d2));
            }
        }

        // ==== l-tile via P @ ones ====
        float Lt[4] = {0.f, 0.f, 0.f, 0.f};
        #pragma unroll
        for (int kc = 0; kc < 4; kc++)
            mma_f16(Lt, ph[kc], ones2);

        // ==== O += P @ Vh ====
        #pragma unroll
        for (int kc = 0; kc < 4; kc++) {
            uint32_t vh[4][4];
            #pragma unroll
            for (int dp = 0; dp < 4; dp++) {
                uint32_t sw = SWZ((uint32_t)((kc * 16 + vrow) * 128 + dp * 32 + vcol));
                ldmatrix_x4_t(vh[dp], kv + 16384 + sw);
            }
            #pragma unroll
            for (int dp = 0; dp < 4; dp++)
                #pragma unroll
                for (int sub = 0; sub < 2; sub++)
                    mma_f16(O[dp * 2 + sub], ph[kc], &vh[dp][sub * 2]);
        }

        l0 += Lt[0];
        l1 += Lt[2];

        if (t < nt - 1) {
            CP_WAIT0();
            __syncthreads();
            if (t < nt - 2) issue_kv(t + 2);
        }
    }
    CP_WAIT0();   // drain any prefetch issued past the final tile

    // ==== finalize & store split ctx ([token][512] fp16 hi/lo) ====
    const float inv0 = 1.f / l0;
    const float inv1 = 1.f / l1;
    const int qrow = qb * 64 + wid * 16 + (lane >> 2);
    const size_t base0 = ((size_t)b * SEQ + qrow) * 512 + h * 64 + (lane & 3) * 2;
    #pragma unroll
    for (int dc = 0; dc < 8; dc++) {
        uint32_t hi, lo;
        split2h(O[dc][0] * inv0, O[dc][1] * inv0, hi, lo);
        *(uint32_t*)(Ch + base0 + dc * 8) = hi;
        *(uint32_t*)(Cl + base0 + dc * 8) = lo;
        split2h(O[dc][2] * inv1, O[dc][3] * inv1, hi, lo);
        *(uint32_t*)(Ch + base0 + 8 * 512 + dc * 8) = hi;
        *(uint32_t*)(Cl + base0 + 8 * 512 + dc * 8) = lo;
    }
}

// ---------------------------------------------------------------------------
// Launch
// ---------------------------------------------------------------------------
extern "C" void kernel_launch(void* const* d_in, const int* in_sizes, int n_in,
                              void* d_out, int out_size)
{
    const float* values = (const float*)d_in[0];
    const float* keys   = (const float*)d_in[1];
    const float* query  = (const float*)d_in[2];
    const int*   mask   = (const int*)d_in[3];
    const float* Wq = (const float*)d_in[4];
    const float* bq = (const float*)d_in[5];
    const float* Wk = (const float*)d_in[6];
    const float* bk = (const float*)d_in[7];
    const float* Wv = (const float*)d_in[8];
    const float* bv = (const float*)d_in[9];
    const float* Wo = (const float*)d_in[10];
    const float* bo = (const float*)d_in[11];
    float* out = (float*)d_out;

    __half *wth, *wtl, *sh, *sl, *ch, *cl, *hh, *hl, *kch, *kcl, *vch;
    int *idx, *nb, *nt;
    float *bc;
    cudaGetSymbolAddress((void**)&wth, g_Wth);
    cudaGetSymbolAddress((void**)&wtl, g_Wtl);
    cudaGetSymbolAddress((void**)&sh,  g_Sh);
    cudaGetSymbolAddress((void**)&sl,  g_Sl);
    cudaGetSymbolAddress((void**)&hh,  g_Hh);
    cudaGetSymbolAddress((void**)&hl,  g_Hl);
    cudaGetSymbolAddress((void**)&ch,  g_Ch);
    cudaGetSymbolAddress((void**)&cl,  g_Cl);
    cudaGetSymbolAddress((void**)&kch, g_Kch);
    cudaGetSymbolAddress((void**)&kcl, g_Kcl);
    cudaGetSymbolAddress((void**)&vch, g_Vch);
    cudaGetSymbolAddress((void**)&idx, g_Idx);
    cudaGetSymbolAddress((void**)&nb,  g_NB);
    cudaGetSymbolAddress((void**)&nt,  g_NT);
    cudaGetSymbolAddress((void**)&bc,  g_Bc);

    cudaFuncSetAttribute(gemm_v4<0>, cudaFuncAttributeMaxDynamicSharedMemorySize, GEMM_SMEM);
    cudaFuncSetAttribute(gemm_v4<1>, cudaFuncAttributeMaxDynamicSharedMemorySize, GEMM_SMEM);
    cudaFuncSetAttribute(attn_mma,   cudaFuncAttributeMaxDynamicSharedMemorySize, ATT_SMEM);

    prep_weights<<<4 * HID * HID / 256, 256>>>(Wq, Wk, Wv, Wo, wth, wtl);
    prep_acts<<<3 * MH / 4 / 256, 256>>>(query, keys, values, sh, sl);
    scan_mask<<<BATCH, 256>>>(mask, idx, nb, nt, bc);

    dim3 gqkv(HID / 64, MROWS / 128, 3);    // (8, 64, 3) = 1536 CTAs, 2/SM
    gemm_v4<1><<<gqkv, 128, GEMM_SMEM>>>(sh, sl, wth, wtl, bq, bk, bv,
                                         nullptr, hh, hl);

    dim3 ggather(BH * SEQ * 8 / 256, 3);    // (2048, 3)
    gather_kv<<<ggather, 256>>>(hh, hl, idx, nb, nt, kch, kcl, vch);

    dim3 agrid(SEQ / 64, HEADS, BATCH);     // (32, 8, 4) = 1024 CTAs, 3/SM
    attn_mma<<<agrid, 128, ATT_SMEM>>>(hh, hl, kch, kcl, vch, bc, nt, ch, cl);

    dim3 gout(HID / 64, MROWS / 128);       // (8, 64) = 512 CTAs, 2/SM
    gemm_v4<0><<<gout, 128, GEMM_SMEM>>>(ch, cl, wth + 3 * HID * HID, wtl + 3 * HID * HID,
                                         bo, nullptr, nullptr, out, nullptr, nullptr);
}

// round 15
// speedup vs baseline: 1.5985x; 1.1548x over previous
#include <cuda_runtime.h>
#include <cuda_bf16.h>
#include <cuda_fp16.h>
#include <cstdint>

// Problem constants
constexpr int BATCH = 4;
constexpr int SEQ   = 2048;
constexpr int HID   = 512;
constexpr int HEADS = 8;
constexpr int HDIM  = 64;
constexpr int MROWS = BATCH * SEQ;           // 8192
constexpr int MH    = MROWS * HID;           // 4194304
constexpr int BH    = BATCH * HEADS;         // 32

// Scratch (device globals; no allocation allowed)
__device__ __half g_Sh[3 * MH];   // activations fp16 hi: z=0 Q (full), z=1 K / z=2 V (COMPACTED rows)
__device__ __half g_Sl[3 * MH];   // fp16 lo residuals
__device__ __half g_Hh[MH];       // head-layout Q fp16 hi: [b*8+h][s][64]
__device__ __half g_Hl[MH];       // head-layout Q fp16 lo
__device__ __half g_Ch[MH];       // split ctx: [token][512]
__device__ __half g_Cl[MH];
__device__ __half g_Wth[4 * HID * HID];   // Wt fp16 hi
__device__ __half g_Wtl[4 * HID * HID];   // Wt fp16 lo
// Mask compaction
__device__ int    g_Idx[BATCH * SEQ];
__device__ int    g_NB[BATCH];            // unmasked count
__device__ int    g_NT[BATCH];            // padded tile count (npad/64)
__device__ float  g_Bc[BATCH * SEQ];      // compacted log2-bias (-SHIFT2 / -1e9 pad)
__device__ __half g_Kch[BH * SEQ * HDIM]; // compacted K hi per bh
__device__ __half g_Kcl[BH * SEQ * HDIM]; // compacted K lo
__device__ __half g_Vch[BH * SEQ * HDIM]; // compacted V hi

#define SWZ(o) ((o) ^ (((o) >> 3) & 0x70))

__device__ __forceinline__ uint32_t smem_u32(const void* p) {
    uint32_t a;
    asm("{ .reg .u64 t; cvta.to.shared.u64 t, %1; cvt.u32.u64 %0, t; }" : "=r"(a) : "l"(p));
    return a;
}
// fp16 split: value = hi + lo to ~2^-22
__device__ __forceinline__ void split2h(float a, float b, uint32_t& hi, uint32_t& lo) {
    __half2 h = __floats2half2_rn(a, b);
    float ra = a - __half2float(__low2half(h));
    float rb = b - __half2float(__high2half(h));
    hi = *reinterpret_cast<uint32_t*>(&h);
    __half2 l = __floats2half2_rn(ra, rb);
    lo = *reinterpret_cast<uint32_t*>(&l);
}
// d = {lo: lo_src, hi: hi_src}
__device__ __forceinline__ uint32_t cvt_f16x2(float hi_src, float lo_src) {
    uint32_t d;
    asm("cvt.rn.f16x2.f32 %0, %1, %2;" : "=r"(d) : "f"(hi_src), "f"(lo_src));
    return d;
}
__device__ __forceinline__ uint32_t exp2_f16x2(uint32_t x) {
    uint32_t d;
    asm("ex2.approx.f16x2 %0, %1;" : "=r"(d) : "r"(x));
    return d;
}
__device__ __forceinline__ void ldmatrix_x4(uint32_t* r, uint32_t addr) {
    asm volatile("ldmatrix.sync.aligned.m8n8.x4.shared.b16 {%0,%1,%2,%3}, [%4];"
                 : "=r"(r[0]), "=r"(r[1]), "=r"(r[2]), "=r"(r[3]) : "r"(addr));
}
__device__ __forceinline__ void ldmatrix_x4_t(uint32_t* r, uint32_t addr) {
    asm volatile("ldmatrix.sync.aligned.m8n8.x4.trans.shared.b16 {%0,%1,%2,%3}, [%4];"
                 : "=r"(r[0]), "=r"(r[1]), "=r"(r[2]), "=r"(r[3]) : "r"(addr));
}
__device__ __forceinline__ void mma_f16(float* d, const uint32_t* a, const uint32_t* b) {
    asm volatile("mma.sync.aligned.m16n8k16.row.col.f32.f16.f16.f32 "
                 "{%0,%1,%2,%3}, {%4,%5,%6,%7}, {%8,%9}, {%0,%1,%2,%3};"
                 : "+f"(d[0]), "+f"(d[1]), "+f"(d[2]), "+f"(d[3])
                 : "r"(a[0]), "r"(a[1]), "r"(a[2]), "r"(a[3]), "r"(b[0]), "r"(b[1]));
}
__device__ __forceinline__ void cp16(uint32_t s, const void* g) {
    asm volatile("cp.async.cg.shared.global [%0], [%1], 16;" :: "r"(s), "l"(g));
}
#define CP_COMMIT() asm volatile("cp.async.commit_group;" ::: "memory")
#define CP_WAIT0()  asm volatile("cp.async.wait_group 0;" ::: "memory")

// Static softmax shift (log2 domain). p = 2^(S' - SHIFT2), S' = log2e * S.
constexpr float SHIFT2 = 6.0f;
constexpr float LOG2E  = 1.4426950408889634f;

// ===========================================================================
// Prep kernels
// ===========================================================================
__global__ void prep_weights(const float* __restrict__ Wq, const float* __restrict__ Wk,
                             const float* __restrict__ Wv, const float* __restrict__ Wo,
                             __half* __restrict__ Wth, __half* __restrict__ Wtl)
{
    int idx = blockIdx.x * blockDim.x + threadIdx.x;
    int mat = idx >> 18;
    int r   = idx & 262143;
    int n   = r >> 9;
    int k   = r & 511;
    const float* W = (mat == 0) ? Wq : (mat == 1) ? Wk : (mat == 2) ? Wv : Wo;
    float w  = W[k * 512 + n];
    __half hi = __float2half_rn(w);
    float lo = w - __half2float(hi);
    Wth[idx] = hi;
    Wtl[idx] = __float2half_rn(lo);
}

// Mask scan: per batch, prefix-sum mask -> compacted index list + counts +
// compacted log2-domain bias (pad region gets -1e9 -> p = 0 exactly).
__global__ void scan_mask(const int* __restrict__ mask, int* __restrict__ idx,
                          int* __restrict__ nbarr, int* __restrict__ ntarr,
                          float* __restrict__ biasc)
{
    __shared__ int ps[256];
    __shared__ int nb_sh;
    const int b = blockIdx.x, tid = threadIdx.x;
    const int* mb = mask + b * SEQ;
    int loc[8], s = 0;
    #pragma unroll
    for (int i = 0; i < 8; i++) { loc[i] = mb[tid * 8 + i]; s += loc[i]; }
    ps[tid] = s;
    __syncthreads();
    for (int d = 1; d < 256; d <<= 1) {
        int v = (tid >= d) ? ps[tid - d] : 0;
        __syncthreads();
        ps[tid] += v;
        __syncthreads();
    }
    int base = ps[tid] - s;
    if (tid == 255) nb_sh = ps[255];
    __syncthreads();
    #pragma unroll
    for (int i = 0; i < 8; i++)
        if (loc[i]) idx[b * SEQ + base++] = tid * 8 + i;
    const int nb   = nb_sh;
    const int npad = (nb + 63) & ~63;
    for (int j = tid; j < SEQ; j += 256)
        biasc[b * SEQ + j] = (j < nb) ? -SHIFT2 : -1e9f;
    if (tid == 0) { nbarr[b] = nb; ntarr[b] = npad >> 6; }
}

// Split activations. z=0: Q rows direct. z=1 (keys) / z=2 (values):
// COMPACTED rows — source row via idx[b][j]; rows j >= nb zero-filled.
__global__ void prep_acts(const float* __restrict__ q, const float* __restrict__ k,
                          const float* __restrict__ v,
                          const int* __restrict__ idx, const int* __restrict__ nbarr,
                          __half* __restrict__ Sh, __half* __restrict__ Sl)
{
    int i = blockIdx.x * blockDim.x + threadIdx.x;   // float4 units
    const int per = MH / 4;
    int z = i / per, u = i - z * per;
    int row = u >> 7;           // token/compacted row (0..8191)
    int cq  = u & 127;          // float4 column
    uint32_t h0 = 0, l0 = 0, h1 = 0, l1 = 0;
    if (z == 0) {
        float4 x = ((const float4*)q)[u];
        split2h(x.x, x.y, h0, l0);
        split2h(x.z, x.w, h1, l1);
    } else {
        int b = row >> 11, j = row & 2047;
        int nb = __ldg(&nbarr[b]);
        if (j < nb) {
            int srow = __ldg(&idx[b * SEQ + j]);
            const float* src = (z == 1) ? k : v;
            float4 x = ((const float4*)src)[(size_t)(b * SEQ + srow) * 128 + cq];
            split2h(x.x, x.y, h0, l0);
            split2h(x.z, x.w, h1, l1);
        }
    }
    ((uint2*)Sh)[i] = make_uint2(h0, h1);
    ((uint2*)Sl)[i] = make_uint2(l0, l1);
}

// ===========================================================================
// HMMA fp16 GEMM v5: CTA 128x64, 4 warps, 2 CTAs/SM, double-buffered.
// MODE 0: fp32 out + bias (output GEMM, 2-term).
// MODE 1: z=0 Q (3-term, scaled, head-layout Oh/Ol);
//         z=1 K (3-term, COMPACTED rows -> Kch/Kcl, CTA early-exit >= npad);
//         z=2 V (2-term, COMPACTED rows -> Vch).
// ===========================================================================
constexpr int GB_AH = 0;
constexpr int GB_AL = 16384;
constexpr int GB_BH = 32768;
constexpr int GB_BL = 40960;
constexpr int GB_SZ = 49152;
constexpr int GEMM_SMEM = 98304;

template<int MODE>
__global__ __launch_bounds__(128, 2)
void gemm_v5(const __half* __restrict__ Ah_, const __half* __restrict__ Al_,
             const __half* __restrict__ Bh_, const __half* __restrict__ Bl_,
             const float* __restrict__ b0, const float* __restrict__ b1,
             const float* __restrict__ b2, const int* __restrict__ ntarr,
             float* __restrict__ C, __half* __restrict__ Oh, __half* __restrict__ Ol,
             __half* __restrict__ Kch, __half* __restrict__ Kcl, __half* __restrict__ Vch)
{
    extern __shared__ __align__(1024) char smem[];
    const uint32_t sb = smem_u32(smem);
    const int tid = threadIdx.x, wid = tid >> 5, lane = tid & 31;
    const int n0 = blockIdx.x * 64, m0 = blockIdx.y * 128;
    const int z  = (MODE == 1) ? blockIdx.z : 0;
    const bool three = (MODE == 1) && (z != 2);

    // Compacted K/V: skip whole CTA if its row block is entirely padding
    if (MODE == 1 && z != 0) {
        const int jb = m0 & 2047;
        if (jb >= __ldg(&ntarr[m0 >> 11]) * 64) return;
    }

    const __half* Ah = Ah_ + (size_t)z * MH;
    const __half* Al = Al_ + (size_t)z * MH;
    const __half* Bh = Bh_ + (size_t)z * HID * HID;
    const __half* Bl = Bl_ + (size_t)z * HID * HID;
    const float* bias = (z == 0) ? b0 : (z == 1) ? b1 : b2;
    const float scale = (MODE == 1 && z == 0) ? 0.125f * LOG2E : 1.0f;

    const int wm = wid & 1;
    const int wn = wid >> 1;
    float acc[4][4][4];
    #pragma unroll
    for (int mt = 0; mt < 4; mt++)
        #pragma unroll
        for (int nt = 0; nt < 4; nt++)
            #pragma unroll
            for (int j = 0; j < 4; j++) acc[mt][nt][j] = 0.f;

    auto issue = [&](int chunk) {
        const int k0 = chunk * 64;
        const uint32_t base = sb + (uint32_t)(chunk & 1) * GB_SZ;
        #pragma unroll
        for (int i = 0; i < 8; i++) {
            const int q = i * 128 + tid;
            const int r = q >> 3, c = q & 7;
            const uint32_t sw = SWZ((uint32_t)(r * 128 + c * 16));
            const size_t go = (size_t)(m0 + r) * 512 + k0 + c * 8;
            cp16(base + GB_AH + sw, Ah + go);
            cp16(base + GB_AL + sw, Al + go);
        }
        #pragma unroll
        for (int i = 0; i < 4; i++) {
            const int q = i * 128 + tid;
            const int r = q >> 3, c = q & 7;
            const uint32_t sw = SWZ((uint32_t)(r * 128 + c * 16));
            const size_t go = (size_t)(n0 + r) * 512 + k0 + c * 8;
            cp16(base + GB_BH + sw, Bh + go);
            if (three) cp16(base + GB_BL + sw, Bl + go);
        }
        CP_COMMIT();
    };

    issue(0);

    const int a_row  = wm * 64 + (lane & 15);
    const int a_cofs = (lane >> 4) * 16;
    const int b_row  = wn * 32 + (lane & 7) + ((lane >> 4) << 3);
    const int b_cofs = ((lane >> 3) & 1) * 16;

    #pragma unroll 1
    for (int c = 0; c < 8; c++) {
        CP_WAIT0();
        __syncthreads();
        if (c < 7) issue(c + 1);
        const uint32_t base = sb + (uint32_t)(c & 1) * GB_SZ;

        #pragma unroll
        for (int ks = 0; ks < 4; ks++) {
            uint32_t ah[4][4], al[4][4], bh[2][4];
            #pragma unroll
            for (int mt = 0; mt < 4; mt++) {
                uint32_t sw = SWZ((uint32_t)((a_row + mt * 16) * 128 + ks * 32 + a_cofs));
                ldmatrix_x4(ah[mt], base + GB_AH + sw);
                ldmatrix_x4(al[mt], base + GB_AL + sw);
            }
            #pragma unroll
            for (int np = 0; np < 2; np++) {
                uint32_t sw = SWZ((uint32_t)((b_row + np * 16) * 128 + ks * 32 + b_cofs));
                ldmatrix_x4(bh[np], base + GB_BH + sw);
            }
            #pragma unroll
            for (int mt = 0; mt < 4; mt++)
                #pragma unroll
                for (int nt = 0; nt < 4; nt++)
                    mma_f16(acc[mt][nt], ah[mt], &bh[nt >> 1][(nt & 1) * 2]);
            #pragma unroll
            for (int mt = 0; mt < 4; mt++)
                #pragma unroll
                for (int nt = 0; nt < 4; nt++)
                    mma_f16(acc[mt][nt], al[mt], &bh[nt >> 1][(nt & 1) * 2]);
            if (three) {
                uint32_t bl[2][4];
                #pragma unroll
                for (int np = 0; np < 2; np++) {
                    uint32_t sw = SWZ((uint32_t)((b_row + np * 16) * 128 + ks * 32 + b_cofs));
                    ldmatrix_x4(bl[np], base + GB_BL + sw);
                }
                #pragma unroll
                for (int mt = 0; mt < 4; mt++)
                    #pragma unroll
                    for (int nt = 0; nt < 4; nt++)
                        mma_f16(acc[mt][nt], ah[mt], &bl[nt >> 1][(nt & 1) * 2]);
            }
        }
    }

    #pragma unroll
    for (int mt = 0; mt < 4; mt++) {
        const int r0 = m0 + wm * 64 + mt * 16 + (lane >> 2);
        #pragma unroll
        for (int nt = 0; nt < 4; nt++) {
            const int c0 = n0 + wn * 32 + nt * 8 + (lane & 3) * 2;
            float2 b = *(const float2*)(bias + c0);
            if (MODE == 0) {
                float2 v0 = make_float2(acc[mt][nt][0] + b.x, acc[mt][nt][1] + b.y);
                float2 v1 = make_float2(acc[mt][nt][2] + b.x, acc[mt][nt][3] + b.y);
                *(float2*)(C + (size_t)r0 * 512 + c0)       = v0;
                *(float2*)(C + (size_t)(r0 + 8) * 512 + c0) = v1;
            } else {
                const int hh = c0 >> 6, d = c0 & 63;
                const int bb = r0 >> 11, s = r0 & 2047;
                const size_t hbase = (((size_t)(bb * HEADS + hh)) * SEQ + s) * 64 + d;
                uint32_t hi, lo;
                split2h((acc[mt][nt][0] + b.x) * scale, (acc[mt][nt][1] + b.y) * scale, hi, lo);
                uint32_t hi2, lo2;
                split2h((acc[mt][nt][2] + b.x) * scale, (acc[mt][nt][3] + b.y) * scale, hi2, lo2);
                if (z == 0) {
                    *(uint32_t*)(Oh + hbase) = hi;
                    *(uint32_t*)(Ol + hbase) = lo;
                    *(uint32_t*)(Oh + hbase + 8 * 64) = hi2;
                    *(uint32_t*)(Ol + hbase + 8 * 64) = lo2;
                } else if (z == 1) {
                    *(uint32_t*)(Kch + hbase) = hi;
                    *(uint32_t*)(Kcl + hbase) = lo;
                    *(uint32_t*)(Kch + hbase + 8 * 64) = hi2;
                    *(uint32_t*)(Kcl + hbase + 8 * 64) = lo2;
                } else {
                    *(uint32_t*)(Vch + hbase) = hi;
                    *(uint32_t*)(Vch + hbase + 8 * 64) = hi2;
                }
            }
        }
    }
}

// ===========================================================================
// fp16 flash attention v9 (unchanged from R14): mask-compacted keys.
// 64 q-rows x nt[b]*64 compacted keys, static-max softmax, 3 CTAs/SM.
// QK 3-term (qh*kh + ql*kh + qh*kl). PV 1-term (ph*vh).
// smem: QH [0,8K) | QL [8K,16K) | buf{0,1} x (Kh|Kl|Vh 8K) [16K,64K)
//       | compacted bias <=2048 f32 [64K,72K)
// ===========================================================================
constexpr int ATT_SMEM = 73728;
constexpr int KV0      = 16384;
constexpr int KVSZ     = 24576;
constexpr int MBIAS    = 65536;

__global__ __launch_bounds__(128, 3)
void attn_mma(const __half* __restrict__ Hh, const __half* __restrict__ Hl,
              const __half* __restrict__ Kch, const __half* __restrict__ Kcl,
              const __half* __restrict__ Vch,
              const float* __restrict__ biasc, const int* __restrict__ ntarr,
              __half* __restrict__ Ch, __half* __restrict__ Cl)
{
    extern __shared__ __align__(1024) char sm[];
    const uint32_t sb = smem_u32(sm);
    const int tid  = threadIdx.x;
    const int wid  = tid >> 5;
    const int lane = tid & 31;
    const int qb = blockIdx.x, h = blockIdx.y, b = blockIdx.z;
    const int bh = b * HEADS + h;
    const int nt = __ldg(&ntarr[b]);

    const __half* Qhp = Hh + ((size_t)bh * SEQ + qb * 64) * 64;
    const __half* Qlp = Hl + ((size_t)bh * SEQ + qb * 64) * 64;
    const __half* Khp = Kch + (size_t)bh * SEQ * 64;
    const __half* Klp = Kcl + (size_t)bh * SEQ * 64;
    const __half* Vhp = Vch + (size_t)bh * SEQ * 64;

    auto issue_kv = [&](int t) {
        const uint32_t dst0 = sb + KV0 + (uint32_t)(t & 1) * KVSZ;
        #pragma unroll
        for (int i = 0; i < 12; i++) {
            const int f   = i * 128 + tid;
            const int buf = i >> 2;                 // 0=Kh, 1=Kl, 2=Vh
            const int r   = (f >> 3) & 63;
            const int c   = f & 7;
            const __half* src = (buf == 0) ? Khp : (buf == 1) ? Klp : Vhp;
            cp16(dst0 + buf * 8192 + SWZ((uint32_t)(r * 128 + c * 16)),
                 src + (size_t)(t * 64 + r) * 64 + c * 8);
        }
        CP_COMMIT();
    };

    issue_kv(0);

    // stage Q (64 rows x 64 fp16 hi/lo) — stays resident all kernel
    {
        const int row = tid >> 1, half = tid & 1;
        const uint4* shp = (const uint4*)(Qhp + row * 64 + half * 32);
        const uint4* slp = (const uint4*)(Qlp + row * 64 + half * 32);
        #pragma unroll
        for (int i = 0; i < 4; i++) {
            uint32_t sw = SWZ((uint32_t)(row * 128 + half * 64 + i * 16));
            *(uint4*)(sm + sw)        = shp[i];
            *(uint4*)(sm + 8192 + sw) = slp[i];
        }
    }
    // compacted bias (covers nt*64 keys, includes -1e9 padding markers)
    for (int i = tid; i < nt * 64; i += 128)
        *(float*)(sm + MBIAS + i * 4) = __ldg(&biasc[b * SEQ + i]);

    CP_WAIT0();
    __syncthreads();
    issue_kv(1);

    float O[8][4];
    #pragma unroll
    for (int dc = 0; dc < 8; dc++)
        #pragma unroll
        for (int j = 0; j < 4; j++) O[dc][j] = 0.f;
    float l0 = 0.f, l1 = 0.f;

    const int arow = wid * 16 + (lane & 15);
    const int acol = (lane >> 4) * 16;
    const int krow = (lane & 7) + ((lane >> 4) << 3);
    const int kcol = ((lane >> 3) & 1) * 16;
    const int vrow = (lane & 15);
    const int vcol = ((lane >> 4) & 1) * 16;
    const uint32_t ones2[2] = {0x3C003C00u, 0x3C003C00u};

    #pragma unroll 1
    for (int t = 0; t < nt; t++) {
        const uint32_t kv = sb + KV0 + (uint32_t)(t & 1) * KVSZ;

        // ==== S' = Q @ K^T (3-term: qh*kh + ql*kh + qh*kl) ====
        float S[8][4];
        #pragma unroll
        for (int nc = 0; nc < 8; nc++)
            #pragma unroll
            for (int j = 0; j < 4; j++) S[nc][j] = 0.f;

        #pragma unroll
        for (int ks = 0; ks < 4; ks++) {
            uint32_t qfh[4], qfl[4], kh[4][4], kl[4][4];
            {
                uint32_t sw = SWZ((uint32_t)(arow * 128 + ks * 32 + acol));
                ldmatrix_x4(qfh, sb + sw);
                ldmatrix_x4(qfl, sb + 8192 + sw);
            }
            #pragma unroll
            for (int np = 0; np < 4; np++) {
                uint32_t sw = SWZ((uint32_t)((np * 16 + krow) * 128 + ks * 32 + kcol));
                ldmatrix_x4(kh[np], kv + sw);
                ldmatrix_x4(kl[np], kv + 8192 + sw);
            }
            #pragma unroll
            for (int np = 0; np < 4; np++)
                #pragma unroll
                for (int sub = 0; sub < 2; sub++)
                    mma_f16(S[np * 2 + sub], qfh, &kh[np][sub * 2]);
            #pragma unroll
            for (int np = 0; np < 4; np++)
                #pragma unroll
                for (int sub = 0; sub < 2; sub++)
                    mma_f16(S[np * 2 + sub], qfl, &kh[np][sub * 2]);
            #pragma unroll
            for (int np = 0; np < 4; np++)
                #pragma unroll
                for (int sub = 0; sub < 2; sub++)
                    mma_f16(S[np * 2 + sub], qfh, &kl[np][sub * 2]);
        }

        // ==== P = 2^(S' + bias') via ex2.approx.f16x2 ====
        uint32_t ph[4][4];
        #pragma unroll
        for (int kc = 0; kc < 4; kc++) {
            #pragma unroll
            for (int sub = 0; sub < 2; sub++) {
                const int nc = kc * 2 + sub;
                float2 bb = *(const float2*)(sm + MBIAS +
                                             (t * 64 + nc * 8 + 2 * (lane & 3)) * 4);
                float d0 = S[nc][0] + bb.x, d1 = S[nc][1] + bb.y;
                float d2 = S[nc][2] + bb.x, d3 = S[nc][3] + bb.y;
                ph[kc][sub * 2]     = exp2_f16x2(cvt_f16x2(d1, d0));
                ph[kc][sub * 2 + 1] = exp2_f16x2(cvt_f16x2(d3, d2));
            }
        }

        // ==== l-tile via P @ ones ====
        float Lt[4] = {0.f, 0.f, 0.f, 0.f};
        #pragma unroll
        for (int kc = 0; kc < 4; kc++)
            mma_f16(Lt, ph[kc], ones2);

        // ==== O += P @ Vh ====
        #pragma unroll
        for (int kc = 0; kc < 4; kc++) {
            uint32_t vh[4][4];
            #pragma unroll
            for (int dp = 0; dp < 4; dp++) {
                uint32_t sw = SWZ((uint32_t)((kc * 16 + vrow) * 128 + dp * 32 + vcol));
                ldmatrix_x4_t(vh[dp], kv + 16384 + sw);
            }
            #pragma unroll
            for (int dp = 0; dp < 4; dp++)
                #pragma unroll
                for (int sub = 0; sub < 2; sub++)
                    mma_f16(O[dp * 2 + sub], ph[kc], &vh[dp][sub * 2]);
        }

        l0 += Lt[0];
        l1 += Lt[2];

        if (t < nt - 1) {
            CP_WAIT0();
            __syncthreads();
            if (t < nt - 2) issue_kv(t + 2);
        }
    }
    CP_WAIT0();   // drain any prefetch issued past the final tile

    // ==== finalize & store split ctx ([token][512] fp16 hi/lo) ====
    const float inv0 = 1.f / l0;
    const float inv1 = 1.f / l1;
    const int qrow = qb * 64 + wid * 16 + (lane >> 2);
    const size_t base0 = ((size_t)b * SEQ + qrow) * 512 + h * 64 + (lane & 3) * 2;
    #pragma unroll
    for (int dc = 0; dc < 8; dc++) {
        uint32_t hi, lo;
        split2h(O[dc][0] * inv0, O[dc][1] * inv0, hi, lo);
        *(uint32_t*)(Ch + base0 + dc * 8) = hi;
        *(uint32_t*)(Cl + base0 + dc * 8) = lo;
        split2h(O[dc][2] * inv1, O[dc][3] * inv1, hi, lo);
        *(uint32_t*)(Ch + base0 + 8 * 512 + dc * 8) = hi;
        *(uint32_t*)(Cl + base0 + 8 * 512 + dc * 8) = lo;
    }
}

// ---------------------------------------------------------------------------
// Launch
// ---------------------------------------------------------------------------
extern "C" void kernel_launch(void* const* d_in, const int* in_sizes, int n_in,
                              void* d_out, int out_size)
{
    const float* values = (const float*)d_in[0];
    const float* keys   = (const float*)d_in[1];
    const float* query  = (const float*)d_in[2];
    const int*   mask   = (const int*)d_in[3];
    const float* Wq = (const float*)d_in[4];
    const float* bq = (const float*)d_in[5];
    const float* Wk = (const float*)d_in[6];
    const float* bk = (const float*)d_in[7];
    const float* Wv = (const float*)d_in[8];
    const float* bv = (const float*)d_in[9];
    const float* Wo = (const float*)d_in[10];
    const float* bo = (const float*)d_in[11];
    float* out = (float*)d_out;

    __half *wth, *wtl, *sh, *sl, *ch, *cl, *hh, *hl, *kch, *kcl, *vch;
    int *idx, *nb, *nt;
    float *bc;
    cudaGetSymbolAddress((void**)&wth, g_Wth);
    cudaGetSymbolAddress((void**)&wtl, g_Wtl);
    cudaGetSymbolAddress((void**)&sh,  g_Sh);
    cudaGetSymbolAddress((void**)&sl,  g_Sl);
    cudaGetSymbolAddress((void**)&hh,  g_Hh);
    cudaGetSymbolAddress((void**)&hl,  g_Hl);
    cudaGetSymbolAddress((void**)&ch,  g_Ch);
    cudaGetSymbolAddress((void**)&cl,  g_Cl);
    cudaGetSymbolAddress((void**)&kch, g_Kch);
    cudaGetSymbolAddress((void**)&kcl, g_Kcl);
    cudaGetSymbolAddress((void**)&vch, g_Vch);
    cudaGetSymbolAddress((void**)&idx, g_Idx);
    cudaGetSymbolAddress((void**)&nb,  g_NB);
    cudaGetSymbolAddress((void**)&nt,  g_NT);
    cudaGetSymbolAddress((void**)&bc,  g_Bc);

    cudaFuncSetAttribute(gemm_v5<0>, cudaFuncAttributeMaxDynamicSharedMemorySize, GEMM_SMEM);
    cudaFuncSetAttribute(gemm_v5<1>, cudaFuncAttributeMaxDynamicSharedMemorySize, GEMM_SMEM);
    cudaFuncSetAttribute(attn_mma,   cudaFuncAttributeMaxDynamicSharedMemorySize, ATT_SMEM);

    prep_weights<<<4 * HID * HID / 256, 256>>>(Wq, Wk, Wv, Wo, wth, wtl);
    scan_mask<<<BATCH, 256>>>(mask, idx, nb, nt, bc);
    prep_acts<<<3 * MH / 4 / 256, 256>>>(query, keys, values, idx, nb, sh, sl);

    dim3 gqkv(HID / 64, MROWS / 128, 3);    // (8, 64, 3); K/V CTAs early-exit past npad
    gemm_v5<1><<<gqkv, 128, GEMM_SMEM>>>(sh, sl, wth, wtl, bq, bk, bv, nt,
                                         nullptr, hh, hl, kch, kcl, vch);

    dim3 agrid(SEQ / 64, HEADS, BATCH);     // (32, 8, 4) = 1024 CTAs, 3/SM
    attn_mma<<<agrid, 128, ATT_SMEM>>>(hh, hl, kch, kcl, vch, bc, nt, ch, cl);

    dim3 gout(HID / 64, MROWS / 128);       // (8, 64) = 512 CTAs, 2/SM
    gemm_v5<0><<<gout, 128, GEMM_SMEM>>>(ch, cl, wth + 3 * HID * HID, wtl + 3 * HID * HID,
                                         bo, nullptr, nullptr, nullptr,
                                         out, nullptr, nullptr, nullptr, nullptr, nullptr);
}

// round 16
// speedup vs baseline: 1.6799x; 1.0509x over previous
#include <cuda_runtime.h>
#include <cuda_bf16.h>
#include <cuda_fp16.h>
#include <cstdint>

// Problem constants
constexpr int BATCH = 4;
constexpr int SEQ   = 2048;
constexpr int HID   = 512;
constexpr int HEADS = 8;
constexpr int HDIM  = 64;
constexpr int MROWS = BATCH * SEQ;           // 8192
constexpr int MH    = MROWS * HID;           // 4194304
constexpr int BH    = BATCH * HEADS;         // 32

// Scratch (device globals; no allocation allowed)
__device__ __half g_Sh[3 * MH];   // activations fp16 hi: z=0 Q (full), z=1 K / z=2 V (COMPACTED rows)
__device__ __half g_Sl[3 * MH];   // fp16 lo residuals
__device__ __half g_Hh[MH];       // head-layout Q fp16 hi: [b*8+h][s][64]
__device__ __half g_Hl[MH];       // head-layout Q fp16 lo
__device__ __half g_Ch[MH];       // split ctx: [token][512]
__device__ __half g_Cl[MH];
__device__ __half g_Wth[4 * HID * HID];   // Wt fp16 hi
__device__ __half g_Wtl[4 * HID * HID];   // Wt fp16 lo
// Mask compaction
__device__ int    g_Idx[BATCH * SEQ];
__device__ int    g_NB[BATCH];            // unmasked count
__device__ int    g_NT[BATCH];            // padded tile count (npad/64)
__device__ float  g_Bc[BATCH * SEQ];      // compacted log2-bias (-SHIFT2 / -1e9 pad)
__device__ __half g_Kch[BH * SEQ * HDIM]; // compacted K hi per bh
__device__ __half g_Kcl[BH * SEQ * HDIM]; // compacted K lo
__device__ __half g_Vch[BH * SEQ * HDIM]; // compacted V hi

#define SWZ(o) ((o) ^ (((o) >> 3) & 0x70))

__device__ __forceinline__ uint32_t smem_u32(const void* p) {
    uint32_t a;
    asm("{ .reg .u64 t; cvta.to.shared.u64 t, %1; cvt.u32.u64 %0, t; }" : "=r"(a) : "l"(p));
    return a;
}
// fp16 split: value = hi + lo to ~2^-22
__device__ __forceinline__ void split2h(float a, float b, uint32_t& hi, uint32_t& lo) {
    __half2 h = __floats2half2_rn(a, b);
    float ra = a - __half2float(__low2half(h));
    float rb = b - __half2float(__high2half(h));
    hi = *reinterpret_cast<uint32_t*>(&h);
    __half2 l = __floats2half2_rn(ra, rb);
    lo = *reinterpret_cast<uint32_t*>(&l);
}
// d = {lo: lo_src, hi: hi_src}
__device__ __forceinline__ uint32_t cvt_f16x2(float hi_src, float lo_src) {
    uint32_t d;
    asm("cvt.rn.f16x2.f32 %0, %1, %2;" : "=r"(d) : "f"(hi_src), "f"(lo_src));
    return d;
}
__device__ __forceinline__ uint32_t exp2_f16x2(uint32_t x) {
    uint32_t d;
    asm("ex2.approx.f16x2 %0, %1;" : "=r"(d) : "r"(x));
    return d;
}
__device__ __forceinline__ void ldmatrix_x4(uint32_t* r, uint32_t addr) {
    asm volatile("ldmatrix.sync.aligned.m8n8.x4.shared.b16 {%0,%1,%2,%3}, [%4];"
                 : "=r"(r[0]), "=r"(r[1]), "=r"(r[2]), "=r"(r[3]) : "r"(addr));
}
__device__ __forceinline__ void ldmatrix_x4_t(uint32_t* r, uint32_t addr) {
    asm volatile("ldmatrix.sync.aligned.m8n8.x4.trans.shared.b16 {%0,%1,%2,%3}, [%4];"
                 : "=r"(r[0]), "=r"(r[1]), "=r"(r[2]), "=r"(r[3]) : "r"(addr));
}
__device__ __forceinline__ void mma_f16(float* d, const uint32_t* a, const uint32_t* b) {
    asm volatile("mma.sync.aligned.m16n8k16.row.col.f32.f16.f16.f32 "
                 "{%0,%1,%2,%3}, {%4,%5,%6,%7}, {%8,%9}, {%0,%1,%2,%3};"
                 : "+f"(d[0]), "+f"(d[1]), "+f"(d[2]), "+f"(d[3])
                 : "r"(a[0]), "r"(a[1]), "r"(a[2]), "r"(a[3]), "r"(b[0]), "r"(b[1]));
}
__device__ __forceinline__ void cp16(uint32_t s, const void* g) {
    asm volatile("cp.async.cg.shared.global [%0], [%1], 16;" :: "r"(s), "l"(g));
}
#define CP_COMMIT() asm volatile("cp.async.commit_group;" ::: "memory")
#define CP_WAIT0()  asm volatile("cp.async.wait_group 0;" ::: "memory")

// Static softmax shift (log2 domain). p = 2^(S' - SHIFT2), S' = log2e * S.
constexpr float SHIFT2 = 6.0f;
constexpr float LOG2E  = 1.4426950408889634f;

// ===========================================================================
// Prep kernels
// ===========================================================================
__global__ void prep_weights(const float* __restrict__ Wq, const float* __restrict__ Wk,
                             const float* __restrict__ Wv, const float* __restrict__ Wo,
                             __half* __restrict__ Wth, __half* __restrict__ Wtl)
{
    int idx = blockIdx.x * blockDim.x + threadIdx.x;
    int mat = idx >> 18;
    int r   = idx & 262143;
    int n   = r >> 9;
    int k   = r & 511;
    const float* W = (mat == 0) ? Wq : (mat == 1) ? Wk : (mat == 2) ? Wv : Wo;
    float w  = W[k * 512 + n];
    __half hi = __float2half_rn(w);
    float lo = w - __half2float(hi);
    Wth[idx] = hi;
    Wtl[idx] = __float2half_rn(lo);
}

// Mask scan: per batch, prefix-sum mask -> compacted index list + counts +
// compacted log2-domain bias (pad region gets -1e9 -> p = 0 exactly).
__global__ void scan_mask(const int* __restrict__ mask, int* __restrict__ idx,
                          int* __restrict__ nbarr, int* __restrict__ ntarr,
                          float* __restrict__ biasc)
{
    __shared__ int ps[256];
    __shared__ int nb_sh;
    const int b = blockIdx.x, tid = threadIdx.x;
    const int* mb = mask + b * SEQ;
    int loc[8], s = 0;
    #pragma unroll
    for (int i = 0; i < 8; i++) { loc[i] = mb[tid * 8 + i]; s += loc[i]; }
    ps[tid] = s;
    __syncthreads();
    for (int d = 1; d < 256; d <<= 1) {
        int v = (tid >= d) ? ps[tid - d] : 0;
        __syncthreads();
        ps[tid] += v;
        __syncthreads();
    }
    int base = ps[tid] - s;
    if (tid == 255) nb_sh = ps[255];
    __syncthreads();
    #pragma unroll
    for (int i = 0; i < 8; i++)
        if (loc[i]) idx[b * SEQ + base++] = tid * 8 + i;
    const int nb   = nb_sh;
    const int npad = (nb + 63) & ~63;
    for (int j = tid; j < SEQ; j += 256)
        biasc[b * SEQ + j] = (j < nb) ? -SHIFT2 : -1e9f;
    if (tid == 0) { nbarr[b] = nb; ntarr[b] = npad >> 6; }
}

// Split activations. z=0: Q rows direct. z=1 (keys) / z=2 (values):
// COMPACTED rows — source row via idx[b][j]; rows j >= nb zero-filled.
__global__ void prep_acts(const float* __restrict__ q, const float* __restrict__ k,
                          const float* __restrict__ v,
                          const int* __restrict__ idx, const int* __restrict__ nbarr,
                          __half* __restrict__ Sh, __half* __restrict__ Sl)
{
    int i = blockIdx.x * blockDim.x + threadIdx.x;   // float4 units
    const int per = MH / 4;
    int z = i / per, u = i - z * per;
    int row = u >> 7;           // token/compacted row (0..8191)
    int cq  = u & 127;          // float4 column
    uint32_t h0 = 0, l0 = 0, h1 = 0, l1 = 0;
    if (z == 0) {
        float4 x = ((const float4*)q)[u];
        split2h(x.x, x.y, h0, l0);
        split2h(x.z, x.w, h1, l1);
    } else {
        int b = row >> 11, j = row & 2047;
        int nb = __ldg(&nbarr[b]);
        if (j < nb) {
            int srow = __ldg(&idx[b * SEQ + j]);
            const float* src = (z == 1) ? k : v;
            float4 x = ((const float4*)src)[(size_t)(b * SEQ + srow) * 128 + cq];
            split2h(x.x, x.y, h0, l0);
            split2h(x.z, x.w, h1, l1);
        }
    }
    ((uint2*)Sh)[i] = make_uint2(h0, h1);
    ((uint2*)Sl)[i] = make_uint2(l0, l1);
}

// ===========================================================================
// HMMA fp16 GEMM v6: CTA tile 64x64, 4 warps (warp tile 32x32), 3 CTAs/SM.
// cp.async double-buffered, term-major, 1 barrier/chunk (K chunk 64).
// MODE 0: fp32 out + bias (output GEMM, 2-term).
// MODE 1: z=0 Q (3-term, scaled, head-layout Oh/Ol);
//         z=1 K (3-term, COMPACTED rows -> Kch/Kcl, CTA early-exit >= npad);
//         z=2 V (2-term, COMPACTED rows -> Vch).
// smem/buffer: AH 8K | AL 8K | BH 8K | BL 8K = 32K; x2 buffers = 64K.
// ===========================================================================
constexpr int GB_AH = 0;
constexpr int GB_AL = 8192;
constexpr int GB_BH = 16384;
constexpr int GB_BL = 24576;
constexpr int GB_SZ = 32768;
constexpr int GEMM_SMEM = 65536;

template<int MODE>
__global__ __launch_bounds__(128, 3)
void gemm_v6(const __half* __restrict__ Ah_, const __half* __restrict__ Al_,
             const __half* __restrict__ Bh_, const __half* __restrict__ Bl_,
             const float* __restrict__ b0, const float* __restrict__ b1,
             const float* __restrict__ b2, const int* __restrict__ ntarr,
             float* __restrict__ C, __half* __restrict__ Oh, __half* __restrict__ Ol,
             __half* __restrict__ Kch, __half* __restrict__ Kcl, __half* __restrict__ Vch)
{
    extern __shared__ __align__(1024) char smem[];
    const uint32_t sb = smem_u32(smem);
    const int tid = threadIdx.x, wid = tid >> 5, lane = tid & 31;
    const int n0 = blockIdx.x * 64, m0 = blockIdx.y * 64;
    const int z  = (MODE == 1) ? blockIdx.z : 0;
    const bool three = (MODE == 1) && (z != 2);

    // Compacted K/V: skip whole CTA if its row block is entirely padding
    if (MODE == 1 && z != 0) {
        const int jb = m0 & 2047;
        if (jb >= __ldg(&ntarr[m0 >> 11]) * 64) return;
    }

    const __half* Ah = Ah_ + (size_t)z * MH;
    const __half* Al = Al_ + (size_t)z * MH;
    const __half* Bh = Bh_ + (size_t)z * HID * HID;
    const __half* Bl = Bl_ + (size_t)z * HID * HID;
    const float* bias = (z == 0) ? b0 : (z == 1) ? b1 : b2;
    const float scale = (MODE == 1 && z == 0) ? 0.125f * LOG2E : 1.0f;

    const int wm = wid & 1;          // 2 M halves of 32 rows
    const int wn = wid >> 1;         // 2 N halves of 32 cols
    float acc[2][4][4];
    #pragma unroll
    for (int mt = 0; mt < 2; mt++)
        #pragma unroll
        for (int nt = 0; nt < 4; nt++)
            #pragma unroll
            for (int j = 0; j < 4; j++) acc[mt][nt][j] = 0.f;

    auto issue = [&](int chunk) {
        const int k0 = chunk * 64;
        const uint32_t base = sb + (uint32_t)(chunk & 1) * GB_SZ;
        // A tile: 64 rows x 64 elems hi+lo = 512 quads each
        #pragma unroll
        for (int i = 0; i < 4; i++) {
            const int q = i * 128 + tid;
            const int r = q >> 3, c = q & 7;
            const uint32_t sw = SWZ((uint32_t)(r * 128 + c * 16));
            const size_t go = (size_t)(m0 + r) * 512 + k0 + c * 8;
            cp16(base + GB_AH + sw, Ah + go);
            cp16(base + GB_AL + sw, Al + go);
        }
        // B tile: 64 rows x 64 elems
        #pragma unroll
        for (int i = 0; i < 4; i++) {
            const int q = i * 128 + tid;
            const int r = q >> 3, c = q & 7;
            const uint32_t sw = SWZ((uint32_t)(r * 128 + c * 16));
            const size_t go = (size_t)(n0 + r) * 512 + k0 + c * 8;
            cp16(base + GB_BH + sw, Bh + go);
            if (three) cp16(base + GB_BL + sw, Bl + go);
        }
        CP_COMMIT();
    };

    issue(0);

    const int a_row  = wm * 32 + (lane & 15);
    const int a_cofs = (lane >> 4) * 16;
    const int b_row  = wn * 32 + (lane & 7) + ((lane >> 4) << 3);
    const int b_cofs = ((lane >> 3) & 1) * 16;

    #pragma unroll 1
    for (int c = 0; c < 8; c++) {
        CP_WAIT0();
        __syncthreads();
        if (c < 7) issue(c + 1);
        const uint32_t base = sb + (uint32_t)(c & 1) * GB_SZ;

        #pragma unroll
        for (int ks = 0; ks < 4; ks++) {
            uint32_t ah[2][4], al[2][4], bh[2][4];
            #pragma unroll
            for (int mt = 0; mt < 2; mt++) {
                uint32_t sw = SWZ((uint32_t)((a_row + mt * 16) * 128 + ks * 32 + a_cofs));
                ldmatrix_x4(ah[mt], base + GB_AH + sw);
                ldmatrix_x4(al[mt], base + GB_AL + sw);
            }
            #pragma unroll
            for (int np = 0; np < 2; np++) {
                uint32_t sw = SWZ((uint32_t)((b_row + np * 16) * 128 + ks * 32 + b_cofs));
                ldmatrix_x4(bh[np], base + GB_BH + sw);
            }
            #pragma unroll
            for (int mt = 0; mt < 2; mt++)
                #pragma unroll
                for (int nt = 0; nt < 4; nt++)
                    mma_f16(acc[mt][nt], ah[mt], &bh[nt >> 1][(nt & 1) * 2]);
            #pragma unroll
            for (int mt = 0; mt < 2; mt++)
                #pragma unroll
                for (int nt = 0; nt < 4; nt++)
                    mma_f16(acc[mt][nt], al[mt], &bh[nt >> 1][(nt & 1) * 2]);
            if (three) {
                uint32_t bl[2][4];
                #pragma unroll
                for (int np = 0; np < 2; np++) {
                    uint32_t sw = SWZ((uint32_t)((b_row + np * 16) * 128 + ks * 32 + b_cofs));
                    ldmatrix_x4(bl[np], base + GB_BL + sw);
                }
                #pragma unroll
                for (int mt = 0; mt < 2; mt++)
                    #pragma unroll
                    for (int nt = 0; nt < 4; nt++)
                        mma_f16(acc[mt][nt], ah[mt], &bl[nt >> 1][(nt & 1) * 2]);
            }
        }
    }

    #pragma unroll
    for (int mt = 0; mt < 2; mt++) {
        const int r0 = m0 + wm * 32 + mt * 16 + (lane >> 2);
        #pragma unroll
        for (int nt = 0; nt < 4; nt++) {
            const int c0 = n0 + wn * 32 + nt * 8 + (lane & 3) * 2;
            float2 b = *(const float2*)(bias + c0);
            if (MODE == 0) {
                float2 v0 = make_float2(acc[mt][nt][0] + b.x, acc[mt][nt][1] + b.y);
                float2 v1 = make_float2(acc[mt][nt][2] + b.x, acc[mt][nt][3] + b.y);
                *(float2*)(C + (size_t)r0 * 512 + c0)       = v0;
                *(float2*)(C + (size_t)(r0 + 8) * 512 + c0) = v1;
            } else {
                const int hh = c0 >> 6, d = c0 & 63;
                const int bb = r0 >> 11, s = r0 & 2047;
                const size_t hbase = (((size_t)(bb * HEADS + hh)) * SEQ + s) * 64 + d;
                uint32_t hi, lo;
                split2h((acc[mt][nt][0] + b.x) * scale, (acc[mt][nt][1] + b.y) * scale, hi, lo);
                uint32_t hi2, lo2;
                split2h((acc[mt][nt][2] + b.x) * scale, (acc[mt][nt][3] + b.y) * scale, hi2, lo2);
                if (z == 0) {
                    *(uint32_t*)(Oh + hbase) = hi;
                    *(uint32_t*)(Ol + hbase) = lo;
                    *(uint32_t*)(Oh + hbase + 8 * 64) = hi2;
                    *(uint32_t*)(Ol + hbase + 8 * 64) = lo2;
                } else if (z == 1) {
                    *(uint32_t*)(Kch + hbase) = hi;
                    *(uint32_t*)(Kcl + hbase) = lo;
                    *(uint32_t*)(Kch + hbase + 8 * 64) = hi2;
                    *(uint32_t*)(Kcl + hbase + 8 * 64) = lo2;
                } else {
                    *(uint32_t*)(Vch + hbase) = hi;
                    *(uint32_t*)(Vch + hbase + 8 * 64) = hi2;
                }
            }
        }
    }
}

// ===========================================================================
// fp16 flash attention v9 (unchanged from R15): mask-compacted keys.
// 64 q-rows x nt[b]*64 compacted keys, static-max softmax, 3 CTAs/SM.
// QK 3-term (qh*kh + ql*kh + qh*kl). PV 1-term (ph*vh).
// smem: QH [0,8K) | QL [8K,16K) | buf{0,1} x (Kh|Kl|Vh 8K) [16K,64K)
//       | compacted bias <=2048 f32 [64K,72K)
// ===========================================================================
constexpr int ATT_SMEM = 73728;
constexpr int KV0      = 16384;
constexpr int KVSZ     = 24576;
constexpr int MBIAS    = 65536;

__global__ __launch_bounds__(128, 3)
void attn_mma(const __half* __restrict__ Hh, const __half* __restrict__ Hl,
              const __half* __restrict__ Kch, const __half* __restrict__ Kcl,
              const __half* __restrict__ Vch,
              const float* __restrict__ biasc, const int* __restrict__ ntarr,
              __half* __restrict__ Ch, __half* __restrict__ Cl)
{
    extern __shared__ __align__(1024) char sm[];
    const uint32_t sb = smem_u32(sm);
    const int tid  = threadIdx.x;
    const int wid  = tid >> 5;
    const int lane = tid & 31;
    const int qb = blockIdx.x, h = blockIdx.y, b = blockIdx.z;
    const int bh = b * HEADS + h;
    const int nt = __ldg(&ntarr[b]);

    const __half* Qhp = Hh + ((size_t)bh * SEQ + qb * 64) * 64;
    const __half* Qlp = Hl + ((size_t)bh * SEQ + qb * 64) * 64;
    const __half* Khp = Kch + (size_t)bh * SEQ * 64;
    const __half* Klp = Kcl + (size_t)bh * SEQ * 64;
    const __half* Vhp = Vch + (size_t)bh * SEQ * 64;

    auto issue_kv = [&](int t) {
        const uint32_t dst0 = sb + KV0 + (uint32_t)(t & 1) * KVSZ;
        #pragma unroll
        for (int i = 0; i < 12; i++) {
            const int f   = i * 128 + tid;
            const int buf = i >> 2;                 // 0=Kh, 1=Kl, 2=Vh
            const int r   = (f >> 3) & 63;
            const int c   = f & 7;
            const __half* src = (buf == 0) ? Khp : (buf == 1) ? Klp : Vhp;
            cp16(dst0 + buf * 8192 + SWZ((uint32_t)(r * 128 + c * 16)),
                 src + (size_t)(t * 64 + r) * 64 + c * 8);
        }
        CP_COMMIT();
    };

    issue_kv(0);

    // stage Q (64 rows x 64 fp16 hi/lo) — stays resident all kernel
    {
        const int row = tid >> 1, half = tid & 1;
        const uint4* shp = (const uint4*)(Qhp + row * 64 + half * 32);
        const uint4* slp = (const uint4*)(Qlp + row * 64 + half * 32);
        #pragma unroll
        for (int i = 0; i < 4; i++) {
            uint32_t sw = SWZ((uint32_t)(row * 128 + half * 64 + i * 16));
            *(uint4*)(sm + sw)        = shp[i];
            *(uint4*)(sm + 8192 + sw) = slp[i];
        }
    }
    // compacted bias (covers nt*64 keys, includes -1e9 padding markers)
    for (int i = tid; i < nt * 64; i += 128)
        *(float*)(sm + MBIAS + i * 4) = __ldg(&biasc[b * SEQ + i]);

    CP_WAIT0();
    __syncthreads();
    issue_kv(1);

    float O[8][4];
    #pragma unroll
    for (int dc = 0; dc < 8; dc++)
        #pragma unroll
        for (int j = 0; j < 4; j++) O[dc][j] = 0.f;
    float l0 = 0.f, l1 = 0.f;

    const int arow = wid * 16 + (lane & 15);
    const int acol = (lane >> 4) * 16;
    const int krow = (lane & 7) + ((lane >> 4) << 3);
    const int kcol = ((lane >> 3) & 1) * 16;
    const int vrow = (lane & 15);
    const int vcol = ((lane >> 4) & 1) * 16;
    const uint32_t ones2[2] = {0x3C003C00u, 0x3C003C00u};

    #pragma unroll 1
    for (int t = 0; t < nt; t++) {
        const uint32_t kv = sb + KV0 + (uint32_t)(t & 1) * KVSZ;

        // ==== S' = Q @ K^T (3-term: qh*kh + ql*kh + qh*kl) ====
        float S[8][4];
        #pragma unroll
        for (int nc = 0; nc < 8; nc++)
            #pragma unroll
            for (int j = 0; j < 4; j++) S[nc][j] = 0.f;

        #pragma unroll
        for (int ks = 0; ks < 4; ks++) {
            uint32_t qfh[4], qfl[4], kh[4][4], kl[4][4];
            {
                uint32_t sw = SWZ((uint32_t)(arow * 128 + ks * 32 + acol));
                ldmatrix_x4(qfh, sb + sw);
                ldmatrix_x4(qfl, sb + 8192 + sw);
            }
            #pragma unroll
            for (int np = 0; np < 4; np++) {
                uint32_t sw = SWZ((uint32_t)((np * 16 + krow) * 128 + ks * 32 + kcol));
                ldmatrix_x4(kh[np], kv + sw);
                ldmatrix_x4(kl[np], kv + 8192 + sw);
            }
            #pragma unroll
            for (int np = 0; np < 4; np++)
                #pragma unroll
                for (int sub = 0; sub < 2; sub++)
                    mma_f16(S[np * 2 + sub], qfh, &kh[np][sub * 2]);
            #pragma unroll
            for (int np = 0; np < 4; np++)
                #pragma unroll
                for (int sub = 0; sub < 2; sub++)
                    mma_f16(S[np * 2 + sub], qfl, &kh[np][sub * 2]);
            #pragma unroll
            for (int np = 0; np < 4; np++)
                #pragma unroll
                for (int sub = 0; sub < 2; sub++)
                    mma_f16(S[np * 2 + sub], qfh, &kl[np][sub * 2]);
        }

        // ==== P = 2^(S' + bias') via ex2.approx.f16x2 ====
        uint32_t ph[4][4];
        #pragma unroll
        for (int kc = 0; kc < 4; kc++) {
            #pragma unroll
            for (int sub = 0; sub < 2; sub++) {
                const int nc = kc * 2 + sub;
                float2 bb = *(const float2*)(sm + MBIAS +
                                             (t * 64 + nc * 8 + 2 * (lane & 3)) * 4);
                float d0 = S[nc][0] + bb.x, d1 = S[nc][1] + bb.y;
                float d2 = S[nc][2] + bb.x, d3 = S[nc][3] + bb.y;
                ph[kc][sub * 2]     = exp2_f16x2(cvt_f16x2(d1, d0));
                ph[kc][sub * 2 + 1] = exp2_f16x2(cvt_f16x2(d3, d2));
            }
        }

        // ==== l-tile via P @ ones ====
        float Lt[4] = {0.f, 0.f, 0.f, 0.f};
        #pragma unroll
        for (int kc = 0; kc < 4; kc++)
            mma_f16(Lt, ph[kc], ones2);

        // ==== O += P @ Vh ====
        #pragma unroll
        for (int kc = 0; kc < 4; kc++) {
            uint32_t vh[4][4];
            #pragma unroll
            for (int dp = 0; dp < 4; dp++) {
                uint32_t sw = SWZ((uint32_t)((kc * 16 + vrow) * 128 + dp * 32 + vcol));
                ldmatrix_x4_t(vh[dp], kv + 16384 + sw);
            }
            #pragma unroll
            for (int dp = 0; dp < 4; dp++)
                #pragma unroll
                for (int sub = 0; sub < 2; sub++)
                    mma_f16(O[dp * 2 + sub], ph[kc], &vh[dp][sub * 2]);
        }

        l0 += Lt[0];
        l1 += Lt[2];

        if (t < nt - 1) {
            CP_WAIT0();
            __syncthreads();
            if (t < nt - 2) issue_kv(t + 2);
        }
    }
    CP_WAIT0();   // drain any prefetch issued past the final tile

    // ==== finalize & store split ctx ([token][512] fp16 hi/lo) ====
    const float inv0 = 1.f / l0;
    const float inv1 = 1.f / l1;
    const int qrow = qb * 64 + wid * 16 + (lane >> 2);
    const size_t base0 = ((size_t)b * SEQ + qrow) * 512 + h * 64 + (lane & 3) * 2;
    #pragma unroll
    for (int dc = 0; dc < 8; dc++) {
        uint32_t hi, lo;
        split2h(O[dc][0] * inv0, O[dc][1] * inv0, hi, lo);
        *(uint32_t*)(Ch + base0 + dc * 8) = hi;
        *(uint32_t*)(Cl + base0 + dc * 8) = lo;
        split2h(O[dc][2] * inv1, O[dc][3] * inv1, hi, lo);
        *(uint32_t*)(Ch + base0 + 8 * 512 + dc * 8) = hi;
        *(uint32_t*)(Cl + base0 + 8 * 512 + dc * 8) = lo;
    }
}

// ---------------------------------------------------------------------------
// Launch
// ---------------------------------------------------------------------------
extern "C" void kernel_launch(void* const* d_in, const int* in_sizes, int n_in,
                              void* d_out, int out_size)
{
    const float* values = (const float*)d_in[0];
    const float* keys   = (const float*)d_in[1];
    const float* query  = (const float*)d_in[2];
    const int*   mask   = (const int*)d_in[3];
    const float* Wq = (const float*)d_in[4];
    const float* bq = (const float*)d_in[5];
    const float* Wk = (const float*)d_in[6];
    const float* bk = (const float*)d_in[7];
    const float* Wv = (const float*)d_in[8];
    const float* bv = (const float*)d_in[9];
    const float* Wo = (const float*)d_in[10];
    const float* bo = (const float*)d_in[11];
    float* out = (float*)d_out;

    __half *wth, *wtl, *sh, *sl, *ch, *cl, *hh, *hl, *kch, *kcl, *vch;
    int *idx, *nb, *nt;
    float *bc;
    cudaGetSymbolAddress((void**)&wth, g_Wth);
    cudaGetSymbolAddress((void**)&wtl, g_Wtl);
    cudaGetSymbolAddress((void**)&sh,  g_Sh);
    cudaGetSymbolAddress((void**)&sl,  g_Sl);
    cudaGetSymbolAddress((void**)&hh,  g_Hh);
    cudaGetSymbolAddress((void**)&hl,  g_Hl);
    cudaGetSymbolAddress((void**)&ch,  g_Ch);
    cudaGetSymbolAddress((void**)&cl,  g_Cl);
    cudaGetSymbolAddress((void**)&kch, g_Kch);
    cudaGetSymbolAddress((void**)&kcl, g_Kcl);
    cudaGetSymbolAddress((void**)&vch, g_Vch);
    cudaGetSymbolAddress((void**)&idx, g_Idx);
    cudaGetSymbolAddress((void**)&nb,  g_NB);
    cudaGetSymbolAddress((void**)&nt,  g_NT);
    cudaGetSymbolAddress((void**)&bc,  g_Bc);

    cudaFuncSetAttribute(gemm_v6<0>, cudaFuncAttributeMaxDynamicSharedMemorySize, GEMM_SMEM);
    cudaFuncSetAttribute(gemm_v6<1>, cudaFuncAttributeMaxDynamicSharedMemorySize, GEMM_SMEM);
    cudaFuncSetAttribute(attn_mma,   cudaFuncAttributeMaxDynamicSharedMemorySize, ATT_SMEM);

    prep_weights<<<4 * HID * HID / 256, 256>>>(Wq, Wk, Wv, Wo, wth, wtl);
    scan_mask<<<BATCH, 256>>>(mask, idx, nb, nt, bc);
    prep_acts<<<3 * MH / 4 / 256, 256>>>(query, keys, values, idx, nb, sh, sl);

    dim3 gqkv(HID / 64, MROWS / 64, 3);     // (8, 128, 3); K/V CTAs early-exit past npad
    gemm_v6<1><<<gqkv, 128, GEMM_SMEM>>>(sh, sl, wth, wtl, bq, bk, bv, nt,
                                         nullptr, hh, hl, kch, kcl, vch);

    dim3 agrid(SEQ / 64, HEADS, BATCH);     // (32, 8, 4) = 1024 CTAs, 3/SM
    attn_mma<<<agrid, 128, ATT_SMEM>>>(hh, hl, kch, kcl, vch, bc, nt, ch, cl);

    dim3 gout(HID / 64, MROWS / 64);        // (8, 128) = 1024 CTAs, 3/SM
    gemm_v6<0><<<gout, 128, GEMM_SMEM>>>(ch, cl, wth + 3 * HID * HID, wtl + 3 * HID * HID,
                                         bo, nullptr, nullptr, nullptr,
                                         out, nullptr, nullptr, nullptr, nullptr, nullptr);
}

// round 17
// speedup vs baseline: 1.7940x; 1.0679x over previous
#include <cuda_runtime.h>
#include <cuda_bf16.h>
#include <cuda_fp16.h>
#include <cstdint>

// Problem constants
constexpr int BATCH = 4;
constexpr int SEQ   = 2048;
constexpr int HID   = 512;
constexpr int HEADS = 8;
constexpr int HDIM  = 64;
constexpr int MROWS = BATCH * SEQ;           // 8192
constexpr int MH    = MROWS * HID;           // 4194304
constexpr int BH    = BATCH * HEADS;         // 32

// Scratch (device globals; no allocation allowed)
__device__ __half g_Sh[3 * MH];   // activations fp16 hi: z=0 Q (full), z=1 K / z=2 V (COMPACTED rows)
__device__ __half g_Sl[3 * MH];   // fp16 lo residuals
__device__ __half g_Hh[MH];       // head-layout Q fp16 hi: [b*8+h][s][64]
__device__ __half g_Hl[MH];       // head-layout Q fp16 lo
__device__ __half g_Ch[MH];       // ctx fp16: [token][512]
__device__ __half g_Wth[4 * HID * HID];   // Wt fp16 hi
__device__ __half g_Wtl[4 * HID * HID];   // Wt fp16 lo
// Mask compaction
__device__ int    g_Idx[BATCH * SEQ];
__device__ int    g_NB[BATCH];            // unmasked count
__device__ int    g_NT[BATCH];            // padded tile count (npad/64)
__device__ __half g_Kch[BH * SEQ * HDIM]; // compacted K hi per bh (pad rows exact 0)
__device__ __half g_Kcl[BH * SEQ * HDIM]; // compacted K lo (pad rows exact 0)
__device__ __half g_Vch[BH * SEQ * HDIM]; // compacted V hi (pad rows exact 0)

#define SWZ(o) ((o) ^ (((o) >> 3) & 0x70))

__device__ __forceinline__ uint32_t smem_u32(const void* p) {
    uint32_t a;
    asm("{ .reg .u64 t; cvta.to.shared.u64 t, %1; cvt.u32.u64 %0, t; }" : "=r"(a) : "l"(p));
    return a;
}
// fp16 split: value = hi + lo to ~2^-22
__device__ __forceinline__ void split2h(float a, float b, uint32_t& hi, uint32_t& lo) {
    __half2 h = __floats2half2_rn(a, b);
    float ra = a - __half2float(__low2half(h));
    float rb = b - __half2float(__high2half(h));
    hi = *reinterpret_cast<uint32_t*>(&h);
    __half2 l = __floats2half2_rn(ra, rb);
    lo = *reinterpret_cast<uint32_t*>(&l);
}
// d = {lo: lo_src, hi: hi_src}
__device__ __forceinline__ uint32_t cvt_f16x2(float hi_src, float lo_src) {
    uint32_t d;
    asm("cvt.rn.f16x2.f32 %0, %1, %2;" : "=r"(d) : "f"(hi_src), "f"(lo_src));
    return d;
}
__device__ __forceinline__ uint32_t exp2_f16x2(uint32_t x) {
    uint32_t d;
    asm("ex2.approx.f16x2 %0, %1;" : "=r"(d) : "r"(x));
    return d;
}
__device__ __forceinline__ void ldmatrix_x4(uint32_t* r, uint32_t addr) {
    asm volatile("ldmatrix.sync.aligned.m8n8.x4.shared.b16 {%0,%1,%2,%3}, [%4];"
                 : "=r"(r[0]), "=r"(r[1]), "=r"(r[2]), "=r"(r[3]) : "r"(addr));
}
__device__ __forceinline__ void ldmatrix_x4_t(uint32_t* r, uint32_t addr) {
    asm volatile("ldmatrix.sync.aligned.m8n8.x4.trans.shared.b16 {%0,%1,%2,%3}, [%4];"
                 : "=r"(r[0]), "=r"(r[1]), "=r"(r[2]), "=r"(r[3]) : "r"(addr));
}
__device__ __forceinline__ void mma_f16(float* d, const uint32_t* a, const uint32_t* b) {
    asm volatile("mma.sync.aligned.m16n8k16.row.col.f32.f16.f16.f32 "
                 "{%0,%1,%2,%3}, {%4,%5,%6,%7}, {%8,%9}, {%0,%1,%2,%3};"
                 : "+f"(d[0]), "+f"(d[1]), "+f"(d[2]), "+f"(d[3])
                 : "r"(a[0]), "r"(a[1]), "r"(a[2]), "r"(a[3]), "r"(b[0]), "r"(b[1]));
}
__device__ __forceinline__ void cp16(uint32_t s, const void* g) {
    asm volatile("cp.async.cg.shared.global [%0], [%1], 16;" :: "r"(s), "l"(g));
}
#define CP_COMMIT() asm volatile("cp.async.commit_group;" ::: "memory")
#define CP_WAIT0()  asm volatile("cp.async.wait_group 0;" ::: "memory")

// Static softmax shift (log2 domain). p = 2^(S' - SHIFT2), S' = log2e * S.
constexpr float SHIFT2 = 6.0f;
constexpr float LOG2E  = 1.4426950408889634f;

// ===========================================================================
// Prep kernels
// ===========================================================================
__global__ void prep_weights(const float* __restrict__ Wq, const float* __restrict__ Wk,
                             const float* __restrict__ Wv, const float* __restrict__ Wo,
                             __half* __restrict__ Wth, __half* __restrict__ Wtl)
{
    int idx = blockIdx.x * blockDim.x + threadIdx.x;
    int mat = idx >> 18;
    int r   = idx & 262143;
    int n   = r >> 9;
    int k   = r & 511;
    const float* W = (mat == 0) ? Wq : (mat == 1) ? Wk : (mat == 2) ? Wv : Wo;
    float w  = W[k * 512 + n];
    __half hi = __float2half_rn(w);
    float lo = w - __half2float(hi);
    Wth[idx] = hi;
    Wtl[idx] = __float2half_rn(lo);
}

// Mask scan: per batch, prefix-sum mask -> compacted index list + counts.
__global__ void scan_mask(const int* __restrict__ mask, int* __restrict__ idx,
                          int* __restrict__ nbarr, int* __restrict__ ntarr)
{
    __shared__ int ps[256];
    __shared__ int nb_sh;
    const int b = blockIdx.x, tid = threadIdx.x;
    const int* mb = mask + b * SEQ;
    int loc[8], s = 0;
    #pragma unroll
    for (int i = 0; i < 8; i++) { loc[i] = mb[tid * 8 + i]; s += loc[i]; }
    ps[tid] = s;
    __syncthreads();
    for (int d = 1; d < 256; d <<= 1) {
        int v = (tid >= d) ? ps[tid - d] : 0;
        __syncthreads();
        ps[tid] += v;
        __syncthreads();
    }
    int base = ps[tid] - s;
    if (tid == 255) nb_sh = ps[255];
    __syncthreads();
    #pragma unroll
    for (int i = 0; i < 8; i++)
        if (loc[i]) idx[b * SEQ + base++] = tid * 8 + i;
    if (tid == 0) {
        nbarr[b] = nb_sh;
        ntarr[b] = ((nb_sh + 63) & ~63) >> 6;
    }
}

// Split activations. z=0: Q rows direct. z=1 (keys) / z=2 (values):
// COMPACTED rows — source row via idx[b][j]; rows j >= nb zero-filled.
__global__ void prep_acts(const float* __restrict__ q, const float* __restrict__ k,
                          const float* __restrict__ v,
                          const int* __restrict__ idx, const int* __restrict__ nbarr,
                          __half* __restrict__ Sh, __half* __restrict__ Sl)
{
    int i = blockIdx.x * blockDim.x + threadIdx.x;   // float4 units
    const int per = MH / 4;
    int z = i / per, u = i - z * per;
    int row = u >> 7;
    int cq  = u & 127;
    uint32_t h0 = 0, l0 = 0, h1 = 0, l1 = 0;
    if (z == 0) {
        float4 x = ((const float4*)q)[u];
        split2h(x.x, x.y, h0, l0);
        split2h(x.z, x.w, h1, l1);
    } else {
        int b = row >> 11, j = row & 2047;
        int nb = __ldg(&nbarr[b]);
        if (j < nb) {
            int srow = __ldg(&idx[b * SEQ + j]);
            const float* src = (z == 1) ? k : v;
            float4 x = ((const float4*)src)[(size_t)(b * SEQ + srow) * 128 + cq];
            split2h(x.x, x.y, h0, l0);
            split2h(x.z, x.w, h1, l1);
        }
    }
    ((uint2*)Sh)[i] = make_uint2(h0, h1);
    ((uint2*)Sl)[i] = make_uint2(l0, l1);
}

// ===========================================================================
// HMMA fp16 GEMM v7: CTA tile 64x64, 4 warps (warp tile 32x32).
// MODE 0: 1-term (ah*bh), fp32 out + bias, 4 CTAs/SM (output GEMM).
// MODE 1: 3 CTAs/SM. z=0 Q (3t, scaled, Oh/Ol); z=1 K (3t -> Kch/Kcl);
//         z=2 V (2t -> Vch). K/V: early-exit past npad; pad rows [nb,npad)
//         written as EXACT ZEROS (enables bias-free pad handling downstream).
// smem/buffer: MODE1 AH|AL|BH|BL 8K each = 32K; MODE0 AH|BH = 16K. x2 bufs.
// ===========================================================================
constexpr int GEMM_SMEM1 = 65536;
constexpr int GEMM_SMEM0 = 32768;

template<int MODE>
__global__ __launch_bounds__(128, (MODE == 0) ? 4 : 3)
void gemm_v7(const __half* __restrict__ Ah_, const __half* __restrict__ Al_,
             const __half* __restrict__ Bh_, const __half* __restrict__ Bl_,
             const float* __restrict__ b0, const float* __restrict__ b1,
             const float* __restrict__ b2,
             const int* __restrict__ nbarr, const int* __restrict__ ntarr,
             float* __restrict__ C, __half* __restrict__ Oh, __half* __restrict__ Ol,
             __half* __restrict__ Kch, __half* __restrict__ Kcl, __half* __restrict__ Vch)
{
    constexpr int OAH = 0;
    constexpr int OAL = 8192;                       // MODE1 only
    constexpr int OBH = (MODE == 0) ? 8192 : 16384;
    constexpr int OBL = 24576;                      // MODE1 only
    constexpr int OSZ = (MODE == 0) ? 16384 : 32768;

    extern __shared__ __align__(1024) char smem[];
    const uint32_t sb = smem_u32(smem);
    const int tid = threadIdx.x, wid = tid >> 5, lane = tid & 31;
    const int n0 = blockIdx.x * 64, m0 = blockIdx.y * 64;
    const int z  = (MODE == 1) ? blockIdx.z : 0;
    const bool three = (MODE == 1) && (z != 2);

    if (MODE == 1 && z != 0) {
        const int jb = m0 & 2047;
        if (jb >= __ldg(&ntarr[m0 >> 11]) * 64) return;
    }

    const __half* Ah = Ah_ + (size_t)z * MH;
    const __half* Al = Al_ + (size_t)z * MH;
    const __half* Bh = Bh_ + (size_t)z * HID * HID;
    const __half* Bl = Bl_ + (size_t)z * HID * HID;
    const float* bias = (z == 0) ? b0 : (z == 1) ? b1 : b2;
    const float scale = (MODE == 1 && z == 0) ? 0.125f * LOG2E : 1.0f;

    const int wm = wid & 1;
    const int wn = wid >> 1;
    float acc[2][4][4];
    #pragma unroll
    for (int mt = 0; mt < 2; mt++)
        #pragma unroll
        for (int nt = 0; nt < 4; nt++)
            #pragma unroll
            for (int j = 0; j < 4; j++) acc[mt][nt][j] = 0.f;

    auto issue = [&](int chunk) {
        const int k0 = chunk * 64;
        const uint32_t base = sb + (uint32_t)(chunk & 1) * OSZ;
        #pragma unroll
        for (int i = 0; i < 4; i++) {
            const int q = i * 128 + tid;
            const int r = q >> 3, c = q & 7;
            const uint32_t sw = SWZ((uint32_t)(r * 128 + c * 16));
            const size_t go = (size_t)(m0 + r) * 512 + k0 + c * 8;
            cp16(base + OAH + sw, Ah + go);
            if (MODE == 1) cp16(base + OAL + sw, Al + go);
        }
        #pragma unroll
        for (int i = 0; i < 4; i++) {
            const int q = i * 128 + tid;
            const int r = q >> 3, c = q & 7;
            const uint32_t sw = SWZ((uint32_t)(r * 128 + c * 16));
            const size_t go = (size_t)(n0 + r) * 512 + k0 + c * 8;
            cp16(base + OBH + sw, Bh + go);
            if (three) cp16(base + OBL + sw, Bl + go);
        }
        CP_COMMIT();
    };

    issue(0);

    const int a_row  = wm * 32 + (lane & 15);
    const int a_cofs = (lane >> 4) * 16;
    const int b_row  = wn * 32 + (lane & 7) + ((lane >> 4) << 3);
    const int b_cofs = ((lane >> 3) & 1) * 16;

    #pragma unroll 1
    for (int c = 0; c < 8; c++) {
        CP_WAIT0();
        __syncthreads();
        if (c < 7) issue(c + 1);
        const uint32_t base = sb + (uint32_t)(c & 1) * OSZ;

        #pragma unroll
        for (int ks = 0; ks < 4; ks++) {
            uint32_t ah[2][4], bh[2][4];
            #pragma unroll
            for (int mt = 0; mt < 2; mt++) {
                uint32_t sw = SWZ((uint32_t)((a_row + mt * 16) * 128 + ks * 32 + a_cofs));
                ldmatrix_x4(ah[mt], base + OAH + sw);
            }
            #pragma unroll
            for (int np = 0; np < 2; np++) {
                uint32_t sw = SWZ((uint32_t)((b_row + np * 16) * 128 + ks * 32 + b_cofs));
                ldmatrix_x4(bh[np], base + OBH + sw);
            }
            #pragma unroll
            for (int mt = 0; mt < 2; mt++)
                #pragma unroll
                for (int nt = 0; nt < 4; nt++)
                    mma_f16(acc[mt][nt], ah[mt], &bh[nt >> 1][(nt & 1) * 2]);
            if (MODE == 1) {
                uint32_t al[2][4];
                #pragma unroll
                for (int mt = 0; mt < 2; mt++) {
                    uint32_t sw = SWZ((uint32_t)((a_row + mt * 16) * 128 + ks * 32 + a_cofs));
                    ldmatrix_x4(al[mt], base + OAL + sw);
                }
                #pragma unroll
                for (int mt = 0; mt < 2; mt++)
                    #pragma unroll
                    for (int nt = 0; nt < 4; nt++)
                        mma_f16(acc[mt][nt], al[mt], &bh[nt >> 1][(nt & 1) * 2]);
            }
            if (three) {
                uint32_t bl[2][4];
                #pragma unroll
                for (int np = 0; np < 2; np++) {
                    uint32_t sw = SWZ((uint32_t)((b_row + np * 16) * 128 + ks * 32 + b_cofs));
                    ldmatrix_x4(bl[np], base + OBL + sw);
                }
                #pragma unroll
                for (int mt = 0; mt < 2; mt++)
                    #pragma unroll
                    for (int nt = 0; nt < 4; nt++)
                        mma_f16(acc[mt][nt], ah[mt], &bl[nt >> 1][(nt & 1) * 2]);
            }
        }
    }

    const int nb_b = (MODE == 1 && z != 0) ? __ldg(&nbarr[m0 >> 11]) : 0;

    #pragma unroll
    for (int mt = 0; mt < 2; mt++) {
        const int r0 = m0 + wm * 32 + mt * 16 + (lane >> 2);
        #pragma unroll
        for (int nt = 0; nt < 4; nt++) {
            const int c0 = n0 + wn * 32 + nt * 8 + (lane & 3) * 2;
            float2 b = *(const float2*)(bias + c0);
            if (MODE == 0) {
                float2 v0 = make_float2(acc[mt][nt][0] + b.x, acc[mt][nt][1] + b.y);
                float2 v1 = make_float2(acc[mt][nt][2] + b.x, acc[mt][nt][3] + b.y);
                *(float2*)(C + (size_t)r0 * 512 + c0)       = v0;
                *(float2*)(C + (size_t)(r0 + 8) * 512 + c0) = v1;
            } else {
                const int hh = c0 >> 6, d = c0 & 63;
                const int bb = r0 >> 11, s = r0 & 2047;
                const size_t hbase = (((size_t)(bb * HEADS + hh)) * SEQ + s) * 64 + d;
                uint32_t hi, lo, hi2, lo2;
                split2h((acc[mt][nt][0] + b.x) * scale, (acc[mt][nt][1] + b.y) * scale, hi, lo);
                split2h((acc[mt][nt][2] + b.x) * scale, (acc[mt][nt][3] + b.y) * scale, hi2, lo2);
                if (z != 0) {   // pad rows -> exact zeros (bias-free pad handling)
                    if (s >= nb_b)     { hi = 0; lo = 0; }
                    if (s + 8 >= nb_b) { hi2 = 0; lo2 = 0; }
                }
                if (z == 0) {
                    *(uint32_t*)(Oh + hbase) = hi;
                    *(uint32_t*)(Ol + hbase) = lo;
                    *(uint32_t*)(Oh + hbase + 8 * 64) = hi2;
                    *(uint32_t*)(Ol + hbase + 8 * 64) = lo2;
                } else if (z == 1) {
                    *(uint32_t*)(Kch + hbase) = hi;
                    *(uint32_t*)(Kcl + hbase) = lo;
                    *(uint32_t*)(Kch + hbase + 8 * 64) = hi2;
                    *(uint32_t*)(Kcl + hbase + 8 * 64) = lo2;
                } else {
                    *(uint32_t*)(Vch + hbase) = hi;
                    *(uint32_t*)(Vch + hbase + 8 * 64) = hi2;
                }
            }
        }
    }
}

// ===========================================================================
// fp16 flash attention v10: mask-compacted keys, bias-free.
// p = 2^(S' - 6) with the -6 as an immediate; pad keys (K=V=0 rows) give
// p = 2^-6 exactly -> subtract (npad-nb)*2^-6 from l once at the end.
// 64 q-rows x nt[b]*64 keys, 3 CTAs/SM. QK 3-term. PV 1-term. ctx fp16 (hi only).
// smem: QH [0,8K) | QL [8K,16K) | buf{0,1} x (Kh|Kl|Vh 8K) [16K,64K)
// ===========================================================================
constexpr int ATT_SMEM = 65536;
constexpr int KV0      = 16384;
constexpr int KVSZ     = 24576;

__global__ __launch_bounds__(128, 3)
void attn_mma(const __half* __restrict__ Hh, const __half* __restrict__ Hl,
              const __half* __restrict__ Kch, const __half* __restrict__ Kcl,
              const __half* __restrict__ Vch,
              const int* __restrict__ nbarr, const int* __restrict__ ntarr,
              __half* __restrict__ Ch)
{
    extern __shared__ __align__(1024) char sm[];
    const uint32_t sb = smem_u32(sm);
    const int tid  = threadIdx.x;
    const int wid  = tid >> 5;
    const int lane = tid & 31;
    const int qb = blockIdx.x, h = blockIdx.y, b = blockIdx.z;
    const int bh = b * HEADS + h;
    const int nt = __ldg(&ntarr[b]);
    const int nb = __ldg(&nbarr[b]);

    const __half* Qhp = Hh + ((size_t)bh * SEQ + qb * 64) * 64;
    const __half* Qlp = Hl + ((size_t)bh * SEQ + qb * 64) * 64;
    const __half* Khp = Kch + (size_t)bh * SEQ * 64;
    const __half* Klp = Kcl + (size_t)bh * SEQ * 64;
    const __half* Vhp = Vch + (size_t)bh * SEQ * 64;

    auto issue_kv = [&](int t) {
        const uint32_t dst0 = sb + KV0 + (uint32_t)(t & 1) * KVSZ;
        #pragma unroll
        for (int i = 0; i < 12; i++) {
            const int f   = i * 128 + tid;
            const int buf = i >> 2;                 // 0=Kh, 1=Kl, 2=Vh
            const int r   = (f >> 3) & 63;
            const int c   = f & 7;
            const __half* src = (buf == 0) ? Khp : (buf == 1) ? Klp : Vhp;
            cp16(dst0 + buf * 8192 + SWZ((uint32_t)(r * 128 + c * 16)),
                 src + (size_t)(t * 64 + r) * 64 + c * 8);
        }
        CP_COMMIT();
    };

    issue_kv(0);

    // stage Q (64 rows x 64 fp16 hi/lo) — stays resident all kernel
    {
        const int row = tid >> 1, half = tid & 1;
        const uint4* shp = (const uint4*)(Qhp + row * 64 + half * 32);
        const uint4* slp = (const uint4*)(Qlp + row * 64 + half * 32);
        #pragma unroll
        for (int i = 0; i < 4; i++) {
            uint32_t sw = SWZ((uint32_t)(row * 128 + half * 64 + i * 16));
            *(uint4*)(sm + sw)        = shp[i];
            *(uint4*)(sm + 8192 + sw) = slp[i];
        }
    }

    CP_WAIT0();
    __syncthreads();
    issue_kv(1);

    float O[8][4];
    #pragma unroll
    for (int dc = 0; dc < 8; dc++)
        #pragma unroll
        for (int j = 0; j < 4; j++) O[dc][j] = 0.f;
    float l0 = 0.f, l1 = 0.f;

    const int arow = wid * 16 + (lane & 15);
    const int acol = (lane >> 4) * 16;
    const int krow = (lane & 7) + ((lane >> 4) << 3);
    const int kcol = ((lane >> 3) & 1) * 16;
    const int vrow = (lane & 15);
    const int vcol = ((lane >> 4) & 1) * 16;
    const uint32_t ones2[2] = {0x3C003C00u, 0x3C003C00u};

    #pragma unroll 1
    for (int t = 0; t < nt; t++) {
        const uint32_t kv = sb + KV0 + (uint32_t)(t & 1) * KVSZ;

        // ==== S' = Q @ K^T (3-term: qh*kh + ql*kh + qh*kl) ====
        float S[8][4];
        #pragma unroll
        for (int nc = 0; nc < 8; nc++)
            #pragma unroll
            for (int j = 0; j < 4; j++) S[nc][j] = 0.f;

        #pragma unroll
        for (int ks = 0; ks < 4; ks++) {
            uint32_t qfh[4], qfl[4], kh[4][4], kl[4][4];
            {
                uint32_t sw = SWZ((uint32_t)(arow * 128 + ks * 32 + acol));
                ldmatrix_x4(qfh, sb + sw);
                ldmatrix_x4(qfl, sb + 8192 + sw);
            }
            #pragma unroll
            for (int np = 0; np < 4; np++) {
                uint32_t sw = SWZ((uint32_t)((np * 16 + krow) * 128 + ks * 32 + kcol));
                ldmatrix_x4(kh[np], kv + sw);
                ldmatrix_x4(kl[np], kv + 8192 + sw);
            }
            #pragma unroll
            for (int np = 0; np < 4; np++)
                #pragma unroll
                for (int sub = 0; sub < 2; sub++)
                    mma_f16(S[np * 2 + sub], qfh, &kh[np][sub * 2]);
            #pragma unroll
            for (int np = 0; np < 4; np++)
                #pragma unroll
                for (int sub = 0; sub < 2; sub++)
                    mma_f16(S[np * 2 + sub], qfl, &kh[np][sub * 2]);
            #pragma unroll
            for (int np = 0; np < 4; np++)
                #pragma unroll
                for (int sub = 0; sub < 2; sub++)
                    mma_f16(S[np * 2 + sub], qfh, &kl[np][sub * 2]);
        }

        // ==== P = 2^(S' - SHIFT2) via ex2.approx.f16x2 (immediate shift) ====
        uint32_t ph[4][4];
        #pragma unroll
        for (int kc = 0; kc < 4; kc++) {
            #pragma unroll
            for (int sub = 0; sub < 2; sub++) {
                const int nc = kc * 2 + sub;
                float d0 = S[nc][0] - SHIFT2, d1 = S[nc][1] - SHIFT2;
                float d2 = S[nc][2] - SHIFT2, d3 = S[nc][3] - SHIFT2;
                ph[kc][sub * 2]     = exp2_f16x2(cvt_f16x2(d1, d0));
                ph[kc][sub * 2 + 1] = exp2_f16x2(cvt_f16x2(d3, d2));
            }
        }

        // ==== l-tile via P @ ones ====
        float Lt[4] = {0.f, 0.f, 0.f, 0.f};
        #pragma unroll
        for (int kc = 0; kc < 4; kc++)
            mma_f16(Lt, ph[kc], ones2);

        // ==== O += P @ Vh ====
        #pragma unroll
        for (int kc = 0; kc < 4; kc++) {
            uint32_t vh[4][4];
            #pragma unroll
            for (int dp = 0; dp < 4; dp++) {
                uint32_t sw = SWZ((uint32_t)((kc * 16 + vrow) * 128 + dp * 32 + vcol));
                ldmatrix_x4_t(vh[dp], kv + 16384 + sw);
            }
            #pragma unroll
            for (int dp = 0; dp < 4; dp++)
                #pragma unroll
                for (int sub = 0; sub < 2; sub++)
                    mma_f16(O[dp * 2 + sub], ph[kc], &vh[dp][sub * 2]);
        }

        l0 += Lt[0];
        l1 += Lt[2];

        if (t < nt - 1) {
            CP_WAIT0();
            __syncthreads();
            if (t < nt - 2) issue_kv(t + 2);
        }
    }
    CP_WAIT0();   // drain any prefetch issued past the final tile

    // pad keys contributed exactly 2^-6 each to l (K rows zero, -6 shift)
    const float lcorr = (float)(nt * 64 - nb) * 0.015625f;
    const float inv0 = 1.f / (l0 - lcorr);
    const float inv1 = 1.f / (l1 - lcorr);
    const int qrow = qb * 64 + wid * 16 + (lane >> 2);
    const size_t base0 = ((size_t)b * SEQ + qrow) * 512 + h * 64 + (lane & 3) * 2;
    #pragma unroll
    for (int dc = 0; dc < 8; dc++) {
        *(uint32_t*)(Ch + base0 + dc * 8) =
            cvt_f16x2(O[dc][1] * inv0, O[dc][0] * inv0);
        *(uint32_t*)(Ch + base0 + 8 * 512 + dc * 8) =
            cvt_f16x2(O[dc][3] * inv1, O[dc][2] * inv1);
    }
}

// ---------------------------------------------------------------------------
// Launch
// ---------------------------------------------------------------------------
extern "C" void kernel_launch(void* const* d_in, const int* in_sizes, int n_in,
                              void* d_out, int out_size)
{
    const float* values = (const float*)d_in[0];
    const float* keys   = (const float*)d_in[1];
    const float* query  = (const float*)d_in[2];
    const int*   mask   = (const int*)d_in[3];
    const float* Wq = (const float*)d_in[4];
    const float* bq = (const float*)d_in[5];
    const float* Wk = (const float*)d_in[6];
    const float* bk = (const float*)d_in[7];
    const float* Wv = (const float*)d_in[8];
    const float* bv = (const float*)d_in[9];
    const float* Wo = (const float*)d_in[10];
    const float* bo = (const float*)d_in[11];
    float* out = (float*)d_out;

    __half *wth, *wtl, *sh, *sl, *ch, *hh, *hl, *kch, *kcl, *vch;
    int *idx, *nb, *nt;
    cudaGetSymbolAddress((void**)&wth, g_Wth);
    cudaGetSymbolAddress((void**)&wtl, g_Wtl);
    cudaGetSymbolAddress((void**)&sh,  g_Sh);
    cudaGetSymbolAddress((void**)&sl,  g_Sl);
    cudaGetSymbolAddress((void**)&hh,  g_Hh);
    cudaGetSymbolAddress((void**)&hl,  g_Hl);
    cudaGetSymbolAddress((void**)&ch,  g_Ch);
    cudaGetSymbolAddress((void**)&kch, g_Kch);
    cudaGetSymbolAddress((void**)&kcl, g_Kcl);
    cudaGetSymbolAddress((void**)&vch, g_Vch);
    cudaGetSymbolAddress((void**)&idx, g_Idx);
    cudaGetSymbolAddress((void**)&nb,  g_NB);
    cudaGetSymbolAddress((void**)&nt,  g_NT);

    cudaFuncSetAttribute(gemm_v7<0>, cudaFuncAttributeMaxDynamicSharedMemorySize, GEMM_SMEM0);
    cudaFuncSetAttribute(gemm_v7<1>, cudaFuncAttributeMaxDynamicSharedMemorySize, GEMM_SMEM1);
    cudaFuncSetAttribute(attn_mma,   cudaFuncAttributeMaxDynamicSharedMemorySize, ATT_SMEM);

    prep_weights<<<4 * HID * HID / 256, 256>>>(Wq, Wk, Wv, Wo, wth, wtl);
    scan_mask<<<BATCH, 256>>>(mask, idx, nb, nt);
    prep_acts<<<3 * MH / 4 / 256, 256>>>(query, keys, values, idx, nb, sh, sl);

    dim3 gqkv(HID / 64, MROWS / 64, 3);     // (8, 128, 3); K/V CTAs early-exit past npad
    gemm_v7<1><<<gqkv, 128, GEMM_SMEM1>>>(sh, sl, wth, wtl, bq, bk, bv, nb, nt,
                                          nullptr, hh, hl, kch, kcl, vch);

    dim3 agrid(SEQ / 64, HEADS, BATCH);     // (32, 8, 4) = 1024 CTAs, 3/SM
    attn_mma<<<agrid, 128, ATT_SMEM>>>(hh, hl, kch, kcl, vch, nb, nt, ch);

    dim3 gout(HID / 64, MROWS / 64);        // (8, 128) = 1024 CTAs, 4/SM
    gemm_v7<0><<<gout, 128, GEMM_SMEM0>>>(ch, nullptr, wth + 3 * HID * HID, nullptr,
                                          bo, nullptr, nullptr, nullptr, nullptr,
                                          out, nullptr, nullptr, nullptr, nullptr, nullptr);
}